// round 5
// baseline (speedup 1.0000x reference)
#include <cuda_runtime.h>
#include <cuda_bf16.h>
#include <math.h>
#include <stdint.h>

// Problem constants
#define BB 2
#define LL 2048
#define DD 2048
#define NHEADS 16
#define KHEADS 8
#define HDIM 128
#define TOK (BB * LL)        // 4096
#define EPSV 1e-6f
#define QKVW 4096            // g_qkv row width (q:0..2047, k:2048..3071, v:3072..4095)

// ---------------------------------------------------------------------------
// Scratch (device globals — no runtime allocation allowed)
// ---------------------------------------------------------------------------
__device__ float g_qkv[(size_t)TOK * QKVW];                         // 67 MB
__device__ __align__(16) __nv_bfloat16 g_xhi[(size_t)TOK * DD];
__device__ __align__(16) __nv_bfloat16 g_xlo[(size_t)TOK * DD];
__device__ __align__(16) __nv_bfloat16 g_qhi[(size_t)TOK * DD];     // rope'd, pre-scaled q
__device__ __align__(16) __nv_bfloat16 g_qlo[(size_t)TOK * DD];
__device__ __align__(16) __nv_bfloat16 g_khi[(size_t)TOK * KHEADS * HDIM];
__device__ __align__(16) __nv_bfloat16 g_klo[(size_t)TOK * KHEADS * HDIM];
__device__ __align__(16) __nv_bfloat16 g_vhi[(size_t)TOK * KHEADS * HDIM];
__device__ __align__(16) __nv_bfloat16 g_vlo[(size_t)TOK * KHEADS * HDIM];
__device__ __align__(16) __nv_bfloat16 g_ohi[(size_t)TOK * DD];     // attention out
__device__ __align__(16) __nv_bfloat16 g_olo[(size_t)TOK * DD];
__device__ __align__(16) __nv_bfloat16 g_wthi[(size_t)QKVW * DD];   // [n][k] qkv weights
__device__ __align__(16) __nv_bfloat16 g_wtlo[(size_t)QKVW * DD];
__device__ __align__(16) __nv_bfloat16 g_wothi[(size_t)DD * DD];    // [n][k] wo
__device__ __align__(16) __nv_bfloat16 g_wotlo[(size_t)DD * DD];

extern __shared__ char dyn_smem[];

// ---------------------------------------------------------------------------
// PTX helpers (family-portable: cp.async / ldmatrix / mma.sync)
// ---------------------------------------------------------------------------
__device__ __forceinline__ uint32_t smem_u32(const void* p) {
    uint32_t a;
    asm("{ .reg .u64 t; cvta.to.shared.u64 t, %1; cvt.u32.u64 %0, t; }"
        : "=r"(a) : "l"(p));
    return a;
}

__device__ __forceinline__ void cp16(uint32_t dst, const void* src) {
    asm volatile("cp.async.cg.shared.global [%0], [%1], 16;" :: "r"(dst), "l"(src));
}
#define CP_COMMIT() asm volatile("cp.async.commit_group;" ::: "memory")
#define CP_WAIT(N)  asm volatile("cp.async.wait_group %0;" :: "n"(N) : "memory")

__device__ __forceinline__ void ldsm4(uint32_t* r, uint32_t a) {
    asm volatile("ldmatrix.sync.aligned.m8n8.x4.shared.b16 {%0,%1,%2,%3}, [%4];"
        : "=r"(r[0]), "=r"(r[1]), "=r"(r[2]), "=r"(r[3]) : "r"(a));
}
__device__ __forceinline__ void ldsm4t(uint32_t* r, uint32_t a) {
    asm volatile("ldmatrix.sync.aligned.m8n8.x4.trans.shared.b16 {%0,%1,%2,%3}, [%4];"
        : "=r"(r[0]), "=r"(r[1]), "=r"(r[2]), "=r"(r[3]) : "r"(a));
}

__device__ __forceinline__ void mma_bf16(float* c, const uint32_t* a, const uint32_t* b) {
    asm volatile(
        "mma.sync.aligned.m16n8k16.row.col.f32.bf16.bf16.f32 "
        "{%0,%1,%2,%3}, {%4,%5,%6,%7}, {%8,%9}, {%0,%1,%2,%3};"
        : "+f"(c[0]), "+f"(c[1]), "+f"(c[2]), "+f"(c[3])
        : "r"(a[0]), "r"(a[1]), "r"(a[2]), "r"(a[3]), "r"(b[0]), "r"(b[1]));
}

__device__ __forceinline__ uint32_t pack_bf2(float x, float y) {
    __nv_bfloat162 t;
    t.x = __float2bfloat16(x);
    t.y = __float2bfloat16(y);
    return *(uint32_t*)&t;
}

// ---------------------------------------------------------------------------
// Conversion kernels
// ---------------------------------------------------------------------------
__global__ void __launch_bounds__(256) transpose_convert_kernel(
    const float* __restrict__ src, int R, int C, int row_off, int which)
{
    __shared__ float t[32][33];
    const int c0 = blockIdx.x * 32;
    const int r0 = blockIdx.y * 32;
    const int tx = threadIdx.x;     // 0..31
    const int ty = threadIdx.y;     // 0..7

#pragma unroll
    for (int j = 0; j < 4; j++)
        t[ty + j * 8][tx] = src[(size_t)(r0 + ty + j * 8) * C + c0 + tx];
    __syncthreads();

    __nv_bfloat16* dhi = which ? g_wothi : g_wthi;
    __nv_bfloat16* dlo = which ? g_wotlo : g_wtlo;
#pragma unroll
    for (int j = 0; j < 4; j++) {
        const int i = ty + j * 8;
        const float v = t[tx][i];
        const __nv_bfloat16 h = __float2bfloat16(v);
        const __nv_bfloat16 l = __float2bfloat16(v - __bfloat162float(h));
        const size_t off = (size_t)(row_off + c0 + i) * DD + r0 + tx;
        dhi[off] = h;
        dlo[off] = l;
    }
}

__global__ void __launch_bounds__(256) convert_split_x_kernel(const float* __restrict__ src)
{
    const size_t i = (size_t)blockIdx.x * blockDim.x + threadIdx.x;
    const size_t n4 = (size_t)TOK * DD / 4;
    if (i >= n4) return;
    const float4 v = ((const float4*)src)[i];
    __nv_bfloat16 h0 = __float2bfloat16(v.x);
    __nv_bfloat16 h1 = __float2bfloat16(v.y);
    __nv_bfloat16 h2 = __float2bfloat16(v.z);
    __nv_bfloat16 h3 = __float2bfloat16(v.w);
    uint2 hp, lp;
    hp.x = pack_bf2(v.x, v.y);
    hp.y = pack_bf2(v.z, v.w);
    lp.x = pack_bf2(v.x - __bfloat162float(h0), v.y - __bfloat162float(h1));
    lp.y = pack_bf2(v.z - __bfloat162float(h2), v.w - __bfloat162float(h3));
    ((uint2*)g_xhi)[i] = hp;
    ((uint2*)g_xlo)[i] = lp;
}

// ---------------------------------------------------------------------------
// split-bf16 warp-MMA GEMM: C[M x N] = A[M x K] * B[N x K]^T, fp32 out
//   CTA tile 128(M) x 256(N), BK=32, 8 warps (2m x 4n), warp tile 64x64.
//   3 products per frag: hi*hi + hi*lo + lo*hi (lo*lo dropped).
//   3-stage cp.async ring, staged wait_group -> 2 stages in flight.
// ---------------------------------------------------------------------------
#define BK 32
#define PITCH 80
#define A_BYTES (128 * PITCH)             // 10240 per split
#define B_BYTES (256 * PITCH)             // 20480 per split
#define STAGE_BYTES (2 * A_BYTES + 2 * B_BYTES)   // 61440
#define GEMM_SMEM_BYTES (3 * STAGE_BYTES)         // 184320

__device__ __forceinline__ void prefetch_stage(
    uint32_t sbase,
    const __nv_bfloat16* __restrict__ Ahi, const __nv_bfloat16* __restrict__ Alo,
    const __nv_bfloat16* __restrict__ Bhi, const __nv_bfloat16* __restrict__ Blo,
    int m0, int n0, int k0, int ldA, int ldB, int tid)
{
    // A: 128 rows x 4 chunks x 2 splits  (2 chunks/thread/split)
#pragma unroll
    for (int j = 0; j < 2; j++) {
        const int id = tid * 2 + j;          // 0..511
        const int r = id >> 2;               // 0..127
        const int c = id & 3;
        const uint32_t soff = r * PITCH + c * 16;
        const size_t ga = (size_t)(m0 + r) * ldA + k0 + c * 8;
        cp16(sbase + soff,           Ahi + ga);
        cp16(sbase + A_BYTES + soff, Alo + ga);
    }
    // B: 256 rows x 4 chunks x 2 splits  (4 chunks/thread/split)
#pragma unroll
    for (int j = 0; j < 4; j++) {
        const int id = tid * 4 + j;          // 0..1023
        const int r = id >> 2;               // 0..255
        const int c = id & 3;
        const uint32_t soff = r * PITCH + c * 16;
        const size_t gb = (size_t)(n0 + r) * ldB + k0 + c * 8;
        cp16(sbase + 2 * A_BYTES + soff,           Bhi + gb);
        cp16(sbase + 2 * A_BYTES + B_BYTES + soff, Blo + gb);
    }
}

__device__ __forceinline__ void gemm_bf16x3_body(
    const __nv_bfloat16* __restrict__ Ahi, const __nv_bfloat16* __restrict__ Alo,
    const __nv_bfloat16* __restrict__ Bhi, const __nv_bfloat16* __restrict__ Blo,
    float* __restrict__ Cc, int K, int ldA, int ldB, int ldC)
{
    const int tid  = threadIdx.x;            // 256 threads
    const int lane = tid & 31;
    const int wid  = tid >> 5;               // 0..7
    const int wm   = wid & 1;                // 2 m-warps (64 rows each)
    const int wn   = wid >> 1;               // 4 n-warps (64 cols each)
    const int m0   = blockIdx.y * 128;
    const int n0   = blockIdx.x * 256;
    const uint32_t smem_base = smem_u32(dyn_smem);

    float c[4][8][4];
#pragma unroll
    for (int i = 0; i < 4; i++)
#pragma unroll
        for (int j = 0; j < 8; j++)
#pragma unroll
            for (int k = 0; k < 4; k++) c[i][j][k] = 0.f;

    const uint32_t a_lane_off =
        (uint32_t)((wm * 64 + (lane & 15)) * PITCH + (lane >> 4) * 16);
    const uint32_t b_lane_off =
        (uint32_t)((wn * 64 + (lane & 7) + ((lane >> 4) << 3)) * PITCH +
                   ((lane >> 3) & 1) * 16);

    const int nk = K / BK;    // 64

    prefetch_stage(smem_base, Ahi, Alo, Bhi, Blo, m0, n0, 0, ldA, ldB, tid);
    CP_COMMIT();
    prefetch_stage(smem_base + STAGE_BYTES, Ahi, Alo, Bhi, Blo, m0, n0, BK, ldA, ldB, tid);
    CP_COMMIT();

    int slot = 0;
    for (int it = 0; it < nk; it++) {
        if (it < nk - 1) { CP_WAIT(1); } else { CP_WAIT(0); }
        __syncthreads();   // all warps done reading the slot we're about to refill

        if (it + 2 < nk) {
            int ps = slot + 2;
            if (ps >= 3) ps -= 3;
            prefetch_stage(smem_base + ps * STAGE_BYTES,
                           Ahi, Alo, Bhi, Blo, m0, n0, (it + 2) * BK, ldA, ldB, tid);
            CP_COMMIT();
        }

        const uint32_t sA = smem_base + slot * STAGE_BYTES;
        const uint32_t sB = sA + 2 * A_BYTES;

#pragma unroll
        for (int kf = 0; kf < 2; kf++) {
            uint32_t a[2][4][4];   // [split][mf][reg]
            uint32_t b[2][4][4];   // [split][nf2][reg]
#pragma unroll
            for (int mf = 0; mf < 4; mf++) {
                const uint32_t ad = sA + a_lane_off + mf * 16 * PITCH + kf * 32;
                ldsm4(a[0][mf], ad);
                ldsm4(a[1][mf], ad + A_BYTES);
            }
#pragma unroll
            for (int nf2 = 0; nf2 < 4; nf2++) {
                const uint32_t bd = sB + b_lane_off + nf2 * 16 * PITCH + kf * 32;
                ldsm4(b[0][nf2], bd);
                ldsm4(b[1][nf2], bd + B_BYTES);
            }
#pragma unroll
            for (int mf = 0; mf < 4; mf++)
#pragma unroll
                for (int nf = 0; nf < 8; nf++) {
                    float* cc = c[mf][nf];
                    const uint32_t* bh = &b[0][nf >> 1][(nf & 1) * 2];
                    const uint32_t* bl = &b[1][nf >> 1][(nf & 1) * 2];
                    mma_bf16(cc, a[0][mf], bh);   // hi*hi
                    mma_bf16(cc, a[0][mf], bl);   // hi*lo
                    mma_bf16(cc, a[1][mf], bh);   // lo*hi
                }
        }

        if (++slot == 3) slot = 0;
    }

    const int row0 = m0 + wm * 64;
    const int col0 = n0 + wn * 64;
    const int gr = lane >> 2;
    const int gc = (lane & 3) * 2;
#pragma unroll
    for (int mf = 0; mf < 4; mf++)
#pragma unroll
        for (int nf = 0; nf < 8; nf++) {
            float* cc = c[mf][nf];
            const int r = row0 + mf * 16 + gr;
            const int cl = col0 + nf * 8 + gc;
            *(float2*)&Cc[(size_t)r * ldC + cl]       = make_float2(cc[0], cc[1]);
            *(float2*)&Cc[(size_t)(r + 8) * ldC + cl] = make_float2(cc[2], cc[3]);
        }
}

__global__ void __launch_bounds__(256, 1) gemm_qkv_kernel() {
    gemm_bf16x3_body(g_xhi, g_xlo, g_wthi, g_wtlo, g_qkv, DD, DD, DD, QKVW);
}
__global__ void __launch_bounds__(256, 1) gemm_out_kernel(float* __restrict__ out) {
    gemm_bf16x3_body(g_ohi, g_olo, g_wothi, g_wotlo, out, DD, DD, DD, DD);
}

// ---------------------------------------------------------------------------
// RMSNorm + RoPE + bf16 hi/lo split. One warp per 128-vector.
// ---------------------------------------------------------------------------
__global__ void __launch_bounds__(256) norm_rope_split_kernel(
    const int* __restrict__ pos_ids,
    const float* __restrict__ q_norm_w,
    const float* __restrict__ k_norm_w)
{
    const int warp = (blockIdx.x * blockDim.x + threadIdx.x) >> 5;
    const int lane = threadIdx.x & 31;
    const int NQ = TOK * NHEADS;
    const int NK = TOK * KHEADS;

    // --- V path: straight split, no norm/rope ---
    if (warp >= NQ + NK) {
        const int idx = warp - NQ - NK;
        if (idx >= TOK * KHEADS) return;
        const int token = idx >> 3;
        const int kh = idx & 7;
        const float* src = g_qkv + (size_t)token * QKVW + 3072 + kh * HDIM + lane * 4;
        const float4 v = *(const float4*)src;
        __nv_bfloat16 h0 = __float2bfloat16(v.x);
        __nv_bfloat16 h1 = __float2bfloat16(v.y);
        __nv_bfloat16 h2 = __float2bfloat16(v.z);
        __nv_bfloat16 h3 = __float2bfloat16(v.w);
        uint2 hp, lp;
        hp.x = pack_bf2(v.x, v.y);
        hp.y = pack_bf2(v.z, v.w);
        lp.x = pack_bf2(v.x - __bfloat162float(h0), v.y - __bfloat162float(h1));
        lp.y = pack_bf2(v.z - __bfloat162float(h2), v.w - __bfloat162float(h3));
        const size_t off = (size_t)token * 1024 + kh * HDIM + lane * 4;
        *(uint2*)&g_vhi[off] = hp;
        *(uint2*)&g_vlo[off] = lp;
        return;
    }

    const bool isq = warp < NQ;
    int token, hidx;
    const float* vecsrc;
    const float* w;
    if (isq) {
        token = warp >> 4;
        hidx = warp & 15;
        vecsrc = g_qkv + (size_t)token * QKVW + hidx * HDIM;
        w = q_norm_w;
    } else {
        const int kv = warp - NQ;
        token = kv >> 3;
        hidx = kv & 7;
        vecsrc = g_qkv + (size_t)token * QKVW + 2048 + hidx * HDIM;
        w = k_norm_w;
    }
    const int pos = pos_ids[token];

    float4 x4 = *(const float4*)&vecsrc[lane * 4];
    float ss = x4.x * x4.x + x4.y * x4.y + x4.z * x4.z + x4.w * x4.w;
#pragma unroll
    for (int m = 16; m; m >>= 1) ss += __shfl_xor_sync(0xffffffffu, ss, m);
    const float rinv = rsqrtf(ss * (1.0f / HDIM) + EPSV);

    float4 w4 = *(const float4*)&w[lane * 4];
    float n0 = x4.x * w4.x * rinv;
    float n1 = x4.y * w4.y * rinv;
    float n2 = x4.z * w4.z * rinv;
    float n3 = x4.w * w4.w * rinv;

    float p0 = __shfl_xor_sync(0xffffffffu, n0, 16);
    float p1 = __shfl_xor_sync(0xffffffffu, n1, 16);
    float p2 = __shfl_xor_sync(0xffffffffu, n2, 16);
    float p3 = __shfl_xor_sync(0xffffffffu, n3, 16);

    const bool firsthalf = lane < 16;
    const int pbase = (lane & 15) * 4;
    const float fpos = (float)pos;
    const double L2T = 19.931568569324174;   // log2(1e6)
    const float QS = isq ? 0.08838834764831845f * 1.4426950408889634f : 1.0f;

    float nv[4] = {n0, n1, n2, n3};
    float pv[4] = {p0, p1, p2, p3};
    float res[4];
#pragma unroll
    for (int j = 0; j < 4; j++) {
        const int p = pbase + j;
        const float inv_ts = exp2f((float)(-(double)p * L2T / 64.0));
        const float ang = fpos * inv_ts;
        float sv, cv;
        sincosf(ang, &sv, &cv);
        const float r = firsthalf ? (nv[j] * cv - pv[j] * sv)
                                  : (nv[j] * cv + pv[j] * sv);
        res[j] = r * QS;
    }

    __nv_bfloat16 h0 = __float2bfloat16(res[0]);
    __nv_bfloat16 h1 = __float2bfloat16(res[1]);
    __nv_bfloat16 h2 = __float2bfloat16(res[2]);
    __nv_bfloat16 h3 = __float2bfloat16(res[3]);
    uint2 hp, lp;
    hp.x = pack_bf2(res[0], res[1]);
    hp.y = pack_bf2(res[2], res[3]);
    lp.x = pack_bf2(res[0] - __bfloat162float(h0), res[1] - __bfloat162float(h1));
    lp.y = pack_bf2(res[2] - __bfloat162float(h2), res[3] - __bfloat162float(h3));

    if (isq) {
        const size_t off = (size_t)token * 2048 + hidx * HDIM + lane * 4;
        *(uint2*)&g_qhi[off] = hp;
        *(uint2*)&g_qlo[off] = lp;
    } else {
        const size_t off = (size_t)token * 1024 + hidx * HDIM + lane * 4;
        *(uint2*)&g_khi[off] = hp;
        *(uint2*)&g_klo[off] = lp;
    }
}

// ---------------------------------------------------------------------------
// Flash attention on tensor cores (mma.sync bf16, split x3).
//   Block: 128 q-rows x (head n, batch b). 8 warps, warp = 16 q-rows.
//   KV tiles of 64, double-buffered cp.async with SPLIT K/V commit groups
//   so the V transfer overlaps the S=QK^T compute.
// ---------------------------------------------------------------------------
#define FLP 272
#define FL_QSZ (128 * FLP)          // 34816
#define FL_KVSZ (64 * FLP)          // 17408
#define FL_STAGE (4 * FL_KVSZ)      // 69632
#define FL_SMEM (2 * FL_QSZ + 2 * FL_STAGE)   // 208896

__device__ __forceinline__ void fl_prefetch_k(
    uint32_t sbase, int b, int kvh, int kv0, int tid)
{
#pragma unroll
    for (int u = 0; u < 8; u++) {
        const int mtx = u >> 2;                      // 0:Khi 1:Klo
        const int row = ((u & 3) << 4) + (tid >> 4); // 0..63
        const int ch = tid & 15;
        const __nv_bfloat16* g = (mtx ? g_klo : g_khi) +
            (size_t)(b * LL + kv0 + row) * 1024 + kvh * HDIM + ch * 8;
        cp16(sbase + mtx * FL_KVSZ + row * FLP + ch * 16, g);
    }
}
__device__ __forceinline__ void fl_prefetch_v(
    uint32_t sbase, int b, int kvh, int kv0, int tid)
{
#pragma unroll
    for (int u = 0; u < 8; u++) {
        const int mtx = u >> 2;                      // 0:Vhi 1:Vlo
        const int row = ((u & 3) << 4) + (tid >> 4);
        const int ch = tid & 15;
        const __nv_bfloat16* g = (mtx ? g_vlo : g_vhi) +
            (size_t)(b * LL + kv0 + row) * 1024 + kvh * HDIM + ch * 8;
        cp16(sbase + (2 + mtx) * FL_KVSZ + row * FLP + ch * 16, g);
    }
}

__global__ void __launch_bounds__(256, 1) flash_kernel()
{
    const int tid = threadIdx.x;
    const int lane = tid & 31;
    const int wid = tid >> 5;
    const int b = blockIdx.z;
    const int n = blockIdx.y;
    const int mt = (int)gridDim.x - 1 - (int)blockIdx.x;  // big tiles launch first
    const int kvh = n >> 1;
    const int m0 = mt * 128;

    const uint32_t sb = smem_u32(dyn_smem);
    const uint32_t sQhi = sb;
    const uint32_t sQlo = sb + FL_QSZ;
    const uint32_t sStage0 = sb + 2 * FL_QSZ;

    // load Q hi/lo + K0 (group 1), V0 (group 2)
#pragma unroll
    for (int u = 0; u < 16; u++) {
        const int mtx = u >> 3;
        const int row = ((u & 7) << 4) + (tid >> 4);
        const int ch = tid & 15;
        const __nv_bfloat16* g = (mtx ? g_qlo : g_qhi) +
            (size_t)(b * LL + m0 + row) * 2048 + n * HDIM + ch * 8;
        cp16((mtx ? sQlo : sQhi) + row * FLP + ch * 16, g);
    }
    fl_prefetch_k(sStage0, b, kvh, 0, tid);
    CP_COMMIT();
    fl_prefetch_v(sStage0, b, kvh, 0, tid);
    CP_COMMIT();

    float acc[16][4];
#pragma unroll
    for (int i = 0; i < 16; i++)
#pragma unroll
        for (int j = 0; j < 4; j++) acc[i][j] = 0.f;
    float m2[2] = {-1e30f, -1e30f};
    float lsum[2] = {0.f, 0.f};

    const uint32_t a_off = (uint32_t)((wid * 16 + (lane & 15)) * FLP + (lane >> 4) * 16);
    const uint32_t bk_off = (uint32_t)(((lane & 7) + ((lane >> 4) << 3)) * FLP +
                                       ((lane >> 3) & 1) * 16);
    const uint32_t v_off = (uint32_t)(((lane & 7) + ((lane >> 3) & 1) * 8) * FLP +
                                      (lane >> 4) * 16);

    const int nkv = 2 * (mt + 1);
    for (int it = 0; it < nkv; it++) {
        CP_WAIT(1);        // K(it) (+Q on it=0) landed; V(it) may be in flight
        __syncthreads();   // everyone done reading the slot we're about to refill
        const bool pf = (it + 1 < nkv);
        if (pf) {
            const uint32_t ns = sStage0 + ((it + 1) & 1) * FL_STAGE;
            fl_prefetch_k(ns, b, kvh, (it + 1) * 64, tid);
            CP_COMMIT();
            fl_prefetch_v(ns, b, kvh, (it + 1) * 64, tid);
            CP_COMMIT();
        }
        const uint32_t sKhi = sStage0 + (it & 1) * FL_STAGE;
        const uint32_t sKlo = sKhi + FL_KVSZ;
        const uint32_t sVhi = sKhi + 2 * FL_KVSZ;
        const uint32_t sVlo = sKhi + 3 * FL_KVSZ;

        // --- S = Q K^T (scores in exp2 domain; q pre-scaled) ---
        float sfr[8][4];
#pragma unroll
        for (int i = 0; i < 8; i++)
#pragma unroll
            for (int j = 0; j < 4; j++) sfr[i][j] = 0.f;

#pragma unroll
        for (int kf = 0; kf < 8; kf++) {
            uint32_t ah[4], al[4];
            ldsm4(ah, sQhi + a_off + kf * 32);
            ldsm4(al, sQlo + a_off + kf * 32);
#pragma unroll
            for (int p2 = 0; p2 < 4; p2++) {
                uint32_t bh[4], bl[4];
                ldsm4(bh, sKhi + bk_off + p2 * 16 * FLP + kf * 32);
                ldsm4(bl, sKlo + bk_off + p2 * 16 * FLP + kf * 32);
                mma_bf16(sfr[2 * p2], ah, bh);
                mma_bf16(sfr[2 * p2], ah, bl);
                mma_bf16(sfr[2 * p2], al, bh);
                mma_bf16(sfr[2 * p2 + 1], ah, bh + 2);
                mma_bf16(sfr[2 * p2 + 1], ah, bl + 2);
                mma_bf16(sfr[2 * p2 + 1], al, bh + 2);
            }
        }

        // --- causal mask (only near-diagonal tiles) ---
        const int rbase = m0 + wid * 16 + (lane >> 2);
        if (it * 64 + 63 > m0 + wid * 16) {
#pragma unroll
            for (int nf = 0; nf < 8; nf++) {
                const int cg = it * 64 + nf * 8 + 2 * (lane & 3);
#pragma unroll
                for (int rg = 0; rg < 4; rg++) {
                    const int row = rbase + (rg >> 1) * 8;
                    const int col = cg + (rg & 1);
                    if (col > row) sfr[nf][rg] = -1e30f;
                }
            }
        }

        // --- online softmax (exp2 domain), warp-local rows ---
#pragma unroll
        for (int h = 0; h < 2; h++) {
            float tm = -1e30f;
#pragma unroll
            for (int nf = 0; nf < 8; nf++)
                tm = fmaxf(tm, fmaxf(sfr[nf][2 * h], sfr[nf][2 * h + 1]));
            tm = fmaxf(tm, __shfl_xor_sync(0xffffffffu, tm, 1));
            tm = fmaxf(tm, __shfl_xor_sync(0xffffffffu, tm, 2));
            const float mn = fmaxf(m2[h], tm);
            const float corr = exp2f(m2[h] - mn);
            m2[h] = mn;
            float rs = 0.f;
#pragma unroll
            for (int nf = 0; nf < 8; nf++) {
                const float e0 = exp2f(sfr[nf][2 * h] - mn);
                const float e1 = exp2f(sfr[nf][2 * h + 1] - mn);
                sfr[nf][2 * h] = e0;
                sfr[nf][2 * h + 1] = e1;
                rs += e0 + e1;
            }
            rs += __shfl_xor_sync(0xffffffffu, rs, 1);
            rs += __shfl_xor_sync(0xffffffffu, rs, 2);
            lsum[h] = lsum[h] * corr + rs;
#pragma unroll
            for (int nf = 0; nf < 16; nf++) {
                acc[nf][2 * h] *= corr;
                acc[nf][2 * h + 1] *= corr;
            }
        }

        // V(it) must be fully landed before PV
        if (pf) { CP_WAIT(2); } else { CP_WAIT(0); }

        // --- O += P V (P frags built from S frags) ---
#pragma unroll
        for (int j = 0; j < 4; j++) {
            uint32_t ph[4], pl[4];
#pragma unroll
            for (int q = 0; q < 4; q++) {
                const int nf = 2 * j + (q >> 1);
                const int rb = (q & 1) * 2;
                const float v0 = sfr[nf][rb], v1 = sfr[nf][rb + 1];
                const __nv_bfloat16 h0 = __float2bfloat16(v0);
                const __nv_bfloat16 h1 = __float2bfloat16(v1);
                ph[q] = pack_bf2(v0, v1);
                pl[q] = pack_bf2(v0 - __bfloat162float(h0), v1 - __bfloat162float(h1));
            }
#pragma unroll
            for (int t = 0; t < 8; t++) {
                uint32_t vh[4], vl[4];
                ldsm4t(vh, sVhi + v_off + j * 16 * FLP + t * 32);
                ldsm4t(vl, sVlo + v_off + j * 16 * FLP + t * 32);
                mma_bf16(acc[2 * t], ph, vh);
                mma_bf16(acc[2 * t], ph, vl);
                mma_bf16(acc[2 * t], pl, vh);
                mma_bf16(acc[2 * t + 1], ph, vh + 2);
                mma_bf16(acc[2 * t + 1], ph, vl + 2);
                mma_bf16(acc[2 * t + 1], pl, vh + 2);
            }
        }
    }

    // --- finalize: /l, split to bf16 hi/lo, store ---
#pragma unroll
    for (int h = 0; h < 2; h++) {
        const float inv = 1.0f / lsum[h];
        const int row = m0 + wid * 16 + (lane >> 2) + h * 8;
        const size_t base = (size_t)(b * LL + row) * 2048 + n * HDIM + 2 * (lane & 3);
#pragma unroll
        for (int nf = 0; nf < 16; nf++) {
            const float v0 = acc[nf][2 * h] * inv;
            const float v1 = acc[nf][2 * h + 1] * inv;
            const __nv_bfloat16 h0 = __float2bfloat16(v0);
            const __nv_bfloat16 h1 = __float2bfloat16(v1);
            *(uint32_t*)&g_ohi[base + nf * 8] = pack_bf2(v0, v1);
            *(uint32_t*)&g_olo[base + nf * 8] =
                pack_bf2(v0 - __bfloat162float(h0), v1 - __bfloat162float(h1));
        }
    }
}

// ---------------------------------------------------------------------------
// Launch
// ---------------------------------------------------------------------------
extern "C" void kernel_launch(void* const* d_in, const int* in_sizes, int n_in,
                              void* d_out, int out_size)
{
    const float* x   = (const float*)d_in[0];
    const int*   pos = (const int*)d_in[1];
    // d_in[2] = attn_mask (causal tril) — implied analytically, unused
    const float* wq  = (const float*)d_in[3];
    const float* wk  = (const float*)d_in[4];
    const float* wv  = (const float*)d_in[5];
    const float* wo  = (const float*)d_in[6];
    const float* qnw = (const float*)d_in[7];
    const float* knw = (const float*)d_in[8];
    float* out = (float*)d_out;

    cudaFuncSetAttribute(gemm_qkv_kernel,
                         cudaFuncAttributeMaxDynamicSharedMemorySize, GEMM_SMEM_BYTES);
    cudaFuncSetAttribute(gemm_out_kernel,
                         cudaFuncAttributeMaxDynamicSharedMemorySize, GEMM_SMEM_BYTES);
    cudaFuncSetAttribute(flash_kernel,
                         cudaFuncAttributeMaxDynamicSharedMemorySize, FL_SMEM);

    // 1. weights -> transposed bf16 hi/lo
    transpose_convert_kernel<<<dim3(64, 64), dim3(32, 8)>>>(wq, 2048, 2048, 0, 0);
    transpose_convert_kernel<<<dim3(32, 64), dim3(32, 8)>>>(wk, 2048, 1024, 2048, 0);
    transpose_convert_kernel<<<dim3(32, 64), dim3(32, 8)>>>(wv, 2048, 1024, 3072, 0);
    transpose_convert_kernel<<<dim3(64, 64), dim3(32, 8)>>>(wo, 2048, 2048, 0, 1);

    // 2. split X
    convert_split_x_kernel<<<(TOK * DD / 4 + 255) / 256, 256>>>(x);

    // 3. QKV projection (CTA tile 128x256)
    gemm_qkv_kernel<<<dim3(QKVW / 256, TOK / 128), 256, GEMM_SMEM_BYTES>>>();

    // 4. RMSNorm + RoPE + split (q,k,v)
    {
        const int nwarps = TOK * (NHEADS + 2 * KHEADS);   // 131072
        const int blocks = nwarps * 32 / 256;
        norm_rope_split_kernel<<<blocks, 256>>>(pos, qnw, knw);
    }

    // 5. Flash attention (tensor cores)
    flash_kernel<<<dim3(LL / 128, NHEADS, BB), 256, FL_SMEM>>>();

    // 6. output projection
    gemm_out_kernel<<<dim3(DD / 256, TOK / 128), 256, GEMM_SMEM_BYTES>>>(out);
}

// round 6
// speedup vs baseline: 1.1263x; 1.1263x over previous
#include <cuda_runtime.h>
#include <cuda_bf16.h>
#include <math.h>
#include <stdint.h>

// Problem constants
#define BB 2
#define LL 2048
#define DD 2048
#define NHEADS 16
#define KHEADS 8
#define HDIM 128
#define TOK (BB * LL)        // 4096
#define EPSV 1e-6f
#define QKVW 4096            // g_qkv row width (q:0..2047, k:2048..3071, v:3072..4095)

// ---------------------------------------------------------------------------
// Scratch (device globals — no runtime allocation allowed)
// ---------------------------------------------------------------------------
__device__ float g_qkv[(size_t)TOK * QKVW];                         // 67 MB
__device__ __align__(16) __nv_bfloat16 g_xhi[(size_t)TOK * DD];
__device__ __align__(16) __nv_bfloat16 g_xlo[(size_t)TOK * DD];
__device__ __align__(16) __nv_bfloat16 g_qhi[(size_t)TOK * DD];     // rope'd, pre-scaled q
__device__ __align__(16) __nv_bfloat16 g_qlo[(size_t)TOK * DD];
__device__ __align__(16) __nv_bfloat16 g_khi[(size_t)TOK * KHEADS * HDIM];
__device__ __align__(16) __nv_bfloat16 g_klo[(size_t)TOK * KHEADS * HDIM];
__device__ __align__(16) __nv_bfloat16 g_vhi[(size_t)TOK * KHEADS * HDIM];
__device__ __align__(16) __nv_bfloat16 g_vlo[(size_t)TOK * KHEADS * HDIM];
__device__ __align__(16) __nv_bfloat16 g_ohi[(size_t)TOK * DD];     // attention out
__device__ __align__(16) __nv_bfloat16 g_olo[(size_t)TOK * DD];
__device__ __align__(16) __nv_bfloat16 g_wthi[(size_t)QKVW * DD];   // [n][k] qkv weights
__device__ __align__(16) __nv_bfloat16 g_wtlo[(size_t)QKVW * DD];
__device__ __align__(16) __nv_bfloat16 g_wothi[(size_t)DD * DD];    // [n][k] wo
__device__ __align__(16) __nv_bfloat16 g_wotlo[(size_t)DD * DD];

extern __shared__ char dyn_smem[];

// ---------------------------------------------------------------------------
// PTX helpers (family-portable: cp.async / ldmatrix / mma.sync)
// ---------------------------------------------------------------------------
__device__ __forceinline__ uint32_t smem_u32(const void* p) {
    uint32_t a;
    asm("{ .reg .u64 t; cvta.to.shared.u64 t, %1; cvt.u32.u64 %0, t; }"
        : "=r"(a) : "l"(p));
    return a;
}

__device__ __forceinline__ void cp16(uint32_t dst, const void* src) {
    asm volatile("cp.async.cg.shared.global [%0], [%1], 16;" :: "r"(dst), "l"(src));
}
#define CP_COMMIT() asm volatile("cp.async.commit_group;" ::: "memory")
#define CP_WAIT(N)  asm volatile("cp.async.wait_group %0;" :: "n"(N) : "memory")

__device__ __forceinline__ void ldsm4(uint32_t* r, uint32_t a) {
    asm volatile("ldmatrix.sync.aligned.m8n8.x4.shared.b16 {%0,%1,%2,%3}, [%4];"
        : "=r"(r[0]), "=r"(r[1]), "=r"(r[2]), "=r"(r[3]) : "r"(a));
}
__device__ __forceinline__ void ldsm4t(uint32_t* r, uint32_t a) {
    asm volatile("ldmatrix.sync.aligned.m8n8.x4.trans.shared.b16 {%0,%1,%2,%3}, [%4];"
        : "=r"(r[0]), "=r"(r[1]), "=r"(r[2]), "=r"(r[3]) : "r"(a));
}

__device__ __forceinline__ void mma_bf16(float* c, const uint32_t* a, const uint32_t* b) {
    asm volatile(
        "mma.sync.aligned.m16n8k16.row.col.f32.bf16.bf16.f32 "
        "{%0,%1,%2,%3}, {%4,%5,%6,%7}, {%8,%9}, {%0,%1,%2,%3};"
        : "+f"(c[0]), "+f"(c[1]), "+f"(c[2]), "+f"(c[3])
        : "r"(a[0]), "r"(a[1]), "r"(a[2]), "r"(a[3]), "r"(b[0]), "r"(b[1]));
}

__device__ __forceinline__ uint32_t pack_bf2(float x, float y) {
    __nv_bfloat162 t;
    t.x = __float2bfloat16(x);
    t.y = __float2bfloat16(y);
    return *(uint32_t*)&t;
}

// ---------------------------------------------------------------------------
// Conversion kernels
// ---------------------------------------------------------------------------
__global__ void __launch_bounds__(256) transpose_convert_kernel(
    const float* __restrict__ src, int R, int C, int row_off, int which)
{
    __shared__ float t[32][33];
    const int c0 = blockIdx.x * 32;
    const int r0 = blockIdx.y * 32;
    const int tx = threadIdx.x;     // 0..31
    const int ty = threadIdx.y;     // 0..7

#pragma unroll
    for (int j = 0; j < 4; j++)
        t[ty + j * 8][tx] = src[(size_t)(r0 + ty + j * 8) * C + c0 + tx];
    __syncthreads();

    __nv_bfloat16* dhi = which ? g_wothi : g_wthi;
    __nv_bfloat16* dlo = which ? g_wotlo : g_wtlo;
#pragma unroll
    for (int j = 0; j < 4; j++) {
        const int i = ty + j * 8;
        const float v = t[tx][i];
        const __nv_bfloat16 h = __float2bfloat16(v);
        const __nv_bfloat16 l = __float2bfloat16(v - __bfloat162float(h));
        const size_t off = (size_t)(row_off + c0 + i) * DD + r0 + tx;
        dhi[off] = h;
        dlo[off] = l;
    }
}

__global__ void __launch_bounds__(256) convert_split_x_kernel(const float* __restrict__ src)
{
    const size_t i = (size_t)blockIdx.x * blockDim.x + threadIdx.x;
    const size_t n4 = (size_t)TOK * DD / 4;
    if (i >= n4) return;
    const float4 v = ((const float4*)src)[i];
    __nv_bfloat16 h0 = __float2bfloat16(v.x);
    __nv_bfloat16 h1 = __float2bfloat16(v.y);
    __nv_bfloat16 h2 = __float2bfloat16(v.z);
    __nv_bfloat16 h3 = __float2bfloat16(v.w);
    uint2 hp, lp;
    hp.x = pack_bf2(v.x, v.y);
    hp.y = pack_bf2(v.z, v.w);
    lp.x = pack_bf2(v.x - __bfloat162float(h0), v.y - __bfloat162float(h1));
    lp.y = pack_bf2(v.z - __bfloat162float(h2), v.w - __bfloat162float(h3));
    ((uint2*)g_xhi)[i] = hp;
    ((uint2*)g_xlo)[i] = lp;
}

// ---------------------------------------------------------------------------
// split-bf16 warp-MMA GEMM: C[M x N] = A[M x K] * B[N x K]^T, fp32 out
//   CTA tile 128(M) x 256(N), BK=32, 512 threads = 16 warps (2m x 8n),
//   warp tile 64x32 (R4's proven warp shape, 4 warps/SMSP for latency hiding).
//   3 products per frag: hi*hi + hi*lo + lo*hi (lo*lo dropped).
//   3-stage cp.async ring, wait_group(1) -> 2 stages in flight.
// ---------------------------------------------------------------------------
#define BK 32
#define PITCH 80
#define A_BYTES (128 * PITCH)             // 10240 per split
#define B_BYTES (256 * PITCH)             // 20480 per split
#define STAGE_BYTES (2 * A_BYTES + 2 * B_BYTES)   // 61440
#define GEMM_SMEM_BYTES (3 * STAGE_BYTES)         // 184320

__device__ __forceinline__ void prefetch_stage(
    uint32_t sbase,
    const __nv_bfloat16* __restrict__ Ahi, const __nv_bfloat16* __restrict__ Alo,
    const __nv_bfloat16* __restrict__ Bhi, const __nv_bfloat16* __restrict__ Blo,
    int m0, int n0, int k0, int ldA, int ldB, int tid)
{
    // A: 128 rows x 4 chunks (16B) x 2 splits; 512 threads -> 1 chunk/thread/split
    {
        const int r = tid >> 2;              // 0..127
        const int c = tid & 3;
        const uint32_t soff = r * PITCH + c * 16;
        const size_t ga = (size_t)(m0 + r) * ldA + k0 + c * 8;
        cp16(sbase + soff,           Ahi + ga);
        cp16(sbase + A_BYTES + soff, Alo + ga);
    }
    // B: 256 rows x 4 chunks x 2 splits; 2 chunks/thread/split
#pragma unroll
    for (int j = 0; j < 2; j++) {
        const int id = tid * 2 + j;          // 0..1023
        const int r = id >> 2;               // 0..255
        const int c = id & 3;
        const uint32_t soff = r * PITCH + c * 16;
        const size_t gb = (size_t)(n0 + r) * ldB + k0 + c * 8;
        cp16(sbase + 2 * A_BYTES + soff,           Bhi + gb);
        cp16(sbase + 2 * A_BYTES + B_BYTES + soff, Blo + gb);
    }
}

__device__ __forceinline__ void gemm_bf16x3_body(
    const __nv_bfloat16* __restrict__ Ahi, const __nv_bfloat16* __restrict__ Alo,
    const __nv_bfloat16* __restrict__ Bhi, const __nv_bfloat16* __restrict__ Blo,
    float* __restrict__ Cc, int K, int ldA, int ldB, int ldC)
{
    const int tid  = threadIdx.x;            // 512 threads
    const int lane = tid & 31;
    const int wid  = tid >> 5;               // 0..15
    const int wm   = wid & 1;                // 2 m-warps (64 rows each)
    const int wn   = wid >> 1;               // 8 n-warps (32 cols each)
    const int m0   = blockIdx.y * 128;
    const int n0   = blockIdx.x * 256;
    const uint32_t smem_base = smem_u32(dyn_smem);

    float c[4][4][4];
#pragma unroll
    for (int i = 0; i < 4; i++)
#pragma unroll
        for (int j = 0; j < 4; j++)
#pragma unroll
            for (int k = 0; k < 4; k++) c[i][j][k] = 0.f;

    const uint32_t a_lane_off =
        (uint32_t)((wm * 64 + (lane & 15)) * PITCH + (lane >> 4) * 16);
    const uint32_t b_lane_off =
        (uint32_t)((wn * 32 + (lane & 7) + ((lane >> 4) << 3)) * PITCH +
                   ((lane >> 3) & 1) * 16);

    const int nk = K / BK;    // 64

    prefetch_stage(smem_base, Ahi, Alo, Bhi, Blo, m0, n0, 0, ldA, ldB, tid);
    CP_COMMIT();
    prefetch_stage(smem_base + STAGE_BYTES, Ahi, Alo, Bhi, Blo, m0, n0, BK, ldA, ldB, tid);
    CP_COMMIT();

    int slot = 0;
    for (int it = 0; it < nk; it++) {
        if (it < nk - 1) { CP_WAIT(1); } else { CP_WAIT(0); }
        __syncthreads();   // all warps done reading the slot we're about to refill

        if (it + 2 < nk) {
            int ps = slot + 2;
            if (ps >= 3) ps -= 3;
            prefetch_stage(smem_base + ps * STAGE_BYTES,
                           Ahi, Alo, Bhi, Blo, m0, n0, (it + 2) * BK, ldA, ldB, tid);
            CP_COMMIT();
        }

        const uint32_t sA = smem_base + slot * STAGE_BYTES;
        const uint32_t sB = sA + 2 * A_BYTES;

#pragma unroll
        for (int kf = 0; kf < 2; kf++) {
            uint32_t b[2][2][4];   // [split][nf2][reg] — held across mf loop
#pragma unroll
            for (int nf2 = 0; nf2 < 2; nf2++) {
                const uint32_t bd = sB + b_lane_off + nf2 * 16 * PITCH + kf * 32;
                ldsm4(b[0][nf2], bd);
                ldsm4(b[1][nf2], bd + B_BYTES);
            }
#pragma unroll
            for (int mf = 0; mf < 4; mf++) {
                uint32_t ah[4], al[4];   // transient per-mf A frags
                const uint32_t ad = sA + a_lane_off + mf * 16 * PITCH + kf * 32;
                ldsm4(ah, ad);
                ldsm4(al, ad + A_BYTES);
#pragma unroll
                for (int nf = 0; nf < 4; nf++) {
                    float* cc = c[mf][nf];
                    const uint32_t* bh = &b[0][nf >> 1][(nf & 1) * 2];
                    const uint32_t* bl = &b[1][nf >> 1][(nf & 1) * 2];
                    mma_bf16(cc, ah, bh);   // hi*hi
                    mma_bf16(cc, ah, bl);   // hi*lo
                    mma_bf16(cc, al, bh);   // lo*hi
                }
            }
        }

        if (++slot == 3) slot = 0;
    }

    const int row0 = m0 + wm * 64;
    const int col0 = n0 + wn * 32;
    const int gr = lane >> 2;
    const int gc = (lane & 3) * 2;
#pragma unroll
    for (int mf = 0; mf < 4; mf++)
#pragma unroll
        for (int nf = 0; nf < 4; nf++) {
            float* cc = c[mf][nf];
            const int r = row0 + mf * 16 + gr;
            const int cl = col0 + nf * 8 + gc;
            *(float2*)&Cc[(size_t)r * ldC + cl]       = make_float2(cc[0], cc[1]);
            *(float2*)&Cc[(size_t)(r + 8) * ldC + cl] = make_float2(cc[2], cc[3]);
        }
}

__global__ void __launch_bounds__(512, 1) gemm_qkv_kernel() {
    gemm_bf16x3_body(g_xhi, g_xlo, g_wthi, g_wtlo, g_qkv, DD, DD, DD, QKVW);
}
__global__ void __launch_bounds__(512, 1) gemm_out_kernel(float* __restrict__ out) {
    gemm_bf16x3_body(g_ohi, g_olo, g_wothi, g_wotlo, out, DD, DD, DD, DD);
}

// ---------------------------------------------------------------------------
// RMSNorm + RoPE + bf16 hi/lo split. One warp per 128-vector.
// ---------------------------------------------------------------------------
__global__ void __launch_bounds__(256) norm_rope_split_kernel(
    const int* __restrict__ pos_ids,
    const float* __restrict__ q_norm_w,
    const float* __restrict__ k_norm_w)
{
    const int warp = (blockIdx.x * blockDim.x + threadIdx.x) >> 5;
    const int lane = threadIdx.x & 31;
    const int NQ = TOK * NHEADS;
    const int NK = TOK * KHEADS;

    // --- V path: straight split, no norm/rope ---
    if (warp >= NQ + NK) {
        const int idx = warp - NQ - NK;
        if (idx >= TOK * KHEADS) return;
        const int token = idx >> 3;
        const int kh = idx & 7;
        const float* src = g_qkv + (size_t)token * QKVW + 3072 + kh * HDIM + lane * 4;
        const float4 v = *(const float4*)src;
        __nv_bfloat16 h0 = __float2bfloat16(v.x);
        __nv_bfloat16 h1 = __float2bfloat16(v.y);
        __nv_bfloat16 h2 = __float2bfloat16(v.z);
        __nv_bfloat16 h3 = __float2bfloat16(v.w);
        uint2 hp, lp;
        hp.x = pack_bf2(v.x, v.y);
        hp.y = pack_bf2(v.z, v.w);
        lp.x = pack_bf2(v.x - __bfloat162float(h0), v.y - __bfloat162float(h1));
        lp.y = pack_bf2(v.z - __bfloat162float(h2), v.w - __bfloat162float(h3));
        const size_t off = (size_t)token * 1024 + kh * HDIM + lane * 4;
        *(uint2*)&g_vhi[off] = hp;
        *(uint2*)&g_vlo[off] = lp;
        return;
    }

    const bool isq = warp < NQ;
    int token, hidx;
    const float* vecsrc;
    const float* w;
    if (isq) {
        token = warp >> 4;
        hidx = warp & 15;
        vecsrc = g_qkv + (size_t)token * QKVW + hidx * HDIM;
        w = q_norm_w;
    } else {
        const int kv = warp - NQ;
        token = kv >> 3;
        hidx = kv & 7;
        vecsrc = g_qkv + (size_t)token * QKVW + 2048 + hidx * HDIM;
        w = k_norm_w;
    }
    const int pos = pos_ids[token];

    float4 x4 = *(const float4*)&vecsrc[lane * 4];
    float ss = x4.x * x4.x + x4.y * x4.y + x4.z * x4.z + x4.w * x4.w;
#pragma unroll
    for (int m = 16; m; m >>= 1) ss += __shfl_xor_sync(0xffffffffu, ss, m);
    const float rinv = rsqrtf(ss * (1.0f / HDIM) + EPSV);

    float4 w4 = *(const float4*)&w[lane * 4];
    float n0 = x4.x * w4.x * rinv;
    float n1 = x4.y * w4.y * rinv;
    float n2 = x4.z * w4.z * rinv;
    float n3 = x4.w * w4.w * rinv;

    float p0 = __shfl_xor_sync(0xffffffffu, n0, 16);
    float p1 = __shfl_xor_sync(0xffffffffu, n1, 16);
    float p2 = __shfl_xor_sync(0xffffffffu, n2, 16);
    float p3 = __shfl_xor_sync(0xffffffffu, n3, 16);

    const bool firsthalf = lane < 16;
    const int pbase = (lane & 15) * 4;
    const float fpos = (float)pos;
    const double L2T = 19.931568569324174;   // log2(1e6)
    const float QS = isq ? 0.08838834764831845f * 1.4426950408889634f : 1.0f;

    float nv[4] = {n0, n1, n2, n3};
    float pv[4] = {p0, p1, p2, p3};
    float res[4];
#pragma unroll
    for (int j = 0; j < 4; j++) {
        const int p = pbase + j;
        const float inv_ts = exp2f((float)(-(double)p * L2T / 64.0));
        const float ang = fpos * inv_ts;
        float sv, cv;
        sincosf(ang, &sv, &cv);
        const float r = firsthalf ? (nv[j] * cv - pv[j] * sv)
                                  : (nv[j] * cv + pv[j] * sv);
        res[j] = r * QS;
    }

    __nv_bfloat16 h0 = __float2bfloat16(res[0]);
    __nv_bfloat16 h1 = __float2bfloat16(res[1]);
    __nv_bfloat16 h2 = __float2bfloat16(res[2]);
    __nv_bfloat16 h3 = __float2bfloat16(res[3]);
    uint2 hp, lp;
    hp.x = pack_bf2(res[0], res[1]);
    hp.y = pack_bf2(res[2], res[3]);
    lp.x = pack_bf2(res[0] - __bfloat162float(h0), res[1] - __bfloat162float(h1));
    lp.y = pack_bf2(res[2] - __bfloat162float(h2), res[3] - __bfloat162float(h3));

    if (isq) {
        const size_t off = (size_t)token * 2048 + hidx * HDIM + lane * 4;
        *(uint2*)&g_qhi[off] = hp;
        *(uint2*)&g_qlo[off] = lp;
    } else {
        const size_t off = (size_t)token * 1024 + hidx * HDIM + lane * 4;
        *(uint2*)&g_khi[off] = hp;
        *(uint2*)&g_klo[off] = lp;
    }
}

// ---------------------------------------------------------------------------
// Flash attention on tensor cores (mma.sync bf16, split x3).
//   Block: 128 q-rows x (head n, batch b). 8 warps, warp = 16 q-rows.
//   KV tiles of 64, double-buffered cp.async with SPLIT K/V commit groups
//   so the V transfer overlaps the S=QK^T compute.
// ---------------------------------------------------------------------------
#define FLP 272
#define FL_QSZ (128 * FLP)          // 34816
#define FL_KVSZ (64 * FLP)          // 17408
#define FL_STAGE (4 * FL_KVSZ)      // 69632
#define FL_SMEM (2 * FL_QSZ + 2 * FL_STAGE)   // 208896

__device__ __forceinline__ void fl_prefetch_k(
    uint32_t sbase, int b, int kvh, int kv0, int tid)
{
#pragma unroll
    for (int u = 0; u < 8; u++) {
        const int mtx = u >> 2;                      // 0:Khi 1:Klo
        const int row = ((u & 3) << 4) + (tid >> 4); // 0..63
        const int ch = tid & 15;
        const __nv_bfloat16* g = (mtx ? g_klo : g_khi) +
            (size_t)(b * LL + kv0 + row) * 1024 + kvh * HDIM + ch * 8;
        cp16(sbase + mtx * FL_KVSZ + row * FLP + ch * 16, g);
    }
}
__device__ __forceinline__ void fl_prefetch_v(
    uint32_t sbase, int b, int kvh, int kv0, int tid)
{
#pragma unroll
    for (int u = 0; u < 8; u++) {
        const int mtx = u >> 2;                      // 0:Vhi 1:Vlo
        const int row = ((u & 3) << 4) + (tid >> 4);
        const int ch = tid & 15;
        const __nv_bfloat16* g = (mtx ? g_vlo : g_vhi) +
            (size_t)(b * LL + kv0 + row) * 1024 + kvh * HDIM + ch * 8;
        cp16(sbase + (2 + mtx) * FL_KVSZ + row * FLP + ch * 16, g);
    }
}

__global__ void __launch_bounds__(256, 1) flash_kernel()
{
    const int tid = threadIdx.x;
    const int lane = tid & 31;
    const int wid = tid >> 5;
    const int b = blockIdx.z;
    const int n = blockIdx.y;
    const int mt = (int)gridDim.x - 1 - (int)blockIdx.x;  // big tiles launch first
    const int kvh = n >> 1;
    const int m0 = mt * 128;

    const uint32_t sb = smem_u32(dyn_smem);
    const uint32_t sQhi = sb;
    const uint32_t sQlo = sb + FL_QSZ;
    const uint32_t sStage0 = sb + 2 * FL_QSZ;

    // load Q hi/lo + K0 (group 1), V0 (group 2)
#pragma unroll
    for (int u = 0; u < 16; u++) {
        const int mtx = u >> 3;
        const int row = ((u & 7) << 4) + (tid >> 4);
        const int ch = tid & 15;
        const __nv_bfloat16* g = (mtx ? g_qlo : g_qhi) +
            (size_t)(b * LL + m0 + row) * 2048 + n * HDIM + ch * 8;
        cp16((mtx ? sQlo : sQhi) + row * FLP + ch * 16, g);
    }
    fl_prefetch_k(sStage0, b, kvh, 0, tid);
    CP_COMMIT();
    fl_prefetch_v(sStage0, b, kvh, 0, tid);
    CP_COMMIT();

    float acc[16][4];
#pragma unroll
    for (int i = 0; i < 16; i++)
#pragma unroll
        for (int j = 0; j < 4; j++) acc[i][j] = 0.f;
    float m2[2] = {-1e30f, -1e30f};
    float lsum[2] = {0.f, 0.f};

    const uint32_t a_off = (uint32_t)((wid * 16 + (lane & 15)) * FLP + (lane >> 4) * 16);
    const uint32_t bk_off = (uint32_t)(((lane & 7) + ((lane >> 4) << 3)) * FLP +
                                       ((lane >> 3) & 1) * 16);
    const uint32_t v_off = (uint32_t)(((lane & 7) + ((lane >> 3) & 1) * 8) * FLP +
                                      (lane >> 4) * 16);

    const int nkv = 2 * (mt + 1);
    for (int it = 0; it < nkv; it++) {
        CP_WAIT(1);        // K(it) (+Q on it=0) landed; V(it) may be in flight
        __syncthreads();   // everyone done reading the slot we're about to refill
        const bool pf = (it + 1 < nkv);
        if (pf) {
            const uint32_t ns = sStage0 + ((it + 1) & 1) * FL_STAGE;
            fl_prefetch_k(ns, b, kvh, (it + 1) * 64, tid);
            CP_COMMIT();
            fl_prefetch_v(ns, b, kvh, (it + 1) * 64, tid);
            CP_COMMIT();
        }
        const uint32_t sKhi = sStage0 + (it & 1) * FL_STAGE;
        const uint32_t sKlo = sKhi + FL_KVSZ;
        const uint32_t sVhi = sKhi + 2 * FL_KVSZ;
        const uint32_t sVlo = sKhi + 3 * FL_KVSZ;

        // --- S = Q K^T (scores in exp2 domain; q pre-scaled) ---
        float sfr[8][4];
#pragma unroll
        for (int i = 0; i < 8; i++)
#pragma unroll
            for (int j = 0; j < 4; j++) sfr[i][j] = 0.f;

#pragma unroll
        for (int kf = 0; kf < 8; kf++) {
            uint32_t ah[4], al[4];
            ldsm4(ah, sQhi + a_off + kf * 32);
            ldsm4(al, sQlo + a_off + kf * 32);
#pragma unroll
            for (int p2 = 0; p2 < 4; p2++) {
                uint32_t bh[4], bl[4];
                ldsm4(bh, sKhi + bk_off + p2 * 16 * FLP + kf * 32);
                ldsm4(bl, sKlo + bk_off + p2 * 16 * FLP + kf * 32);
                mma_bf16(sfr[2 * p2], ah, bh);
                mma_bf16(sfr[2 * p2], ah, bl);
                mma_bf16(sfr[2 * p2], al, bh);
                mma_bf16(sfr[2 * p2 + 1], ah, bh + 2);
                mma_bf16(sfr[2 * p2 + 1], ah, bl + 2);
                mma_bf16(sfr[2 * p2 + 1], al, bh + 2);
            }
        }

        // --- causal mask (only near-diagonal tiles) ---
        const int rbase = m0 + wid * 16 + (lane >> 2);
        if (it * 64 + 63 > m0 + wid * 16) {
#pragma unroll
            for (int nf = 0; nf < 8; nf++) {
                const int cg = it * 64 + nf * 8 + 2 * (lane & 3);
#pragma unroll
                for (int rg = 0; rg < 4; rg++) {
                    const int row = rbase + (rg >> 1) * 8;
                    const int col = cg + (rg & 1);
                    if (col > row) sfr[nf][rg] = -1e30f;
                }
            }
        }

        // --- online softmax (exp2 domain), warp-local rows ---
#pragma unroll
        for (int h = 0; h < 2; h++) {
            float tm = -1e30f;
#pragma unroll
            for (int nf = 0; nf < 8; nf++)
                tm = fmaxf(tm, fmaxf(sfr[nf][2 * h], sfr[nf][2 * h + 1]));
            tm = fmaxf(tm, __shfl_xor_sync(0xffffffffu, tm, 1));
            tm = fmaxf(tm, __shfl_xor_sync(0xffffffffu, tm, 2));
            const float mn = fmaxf(m2[h], tm);
            const float corr = exp2f(m2[h] - mn);
            m2[h] = mn;
            float rs = 0.f;
#pragma unroll
            for (int nf = 0; nf < 8; nf++) {
                const float e0 = exp2f(sfr[nf][2 * h] - mn);
                const float e1 = exp2f(sfr[nf][2 * h + 1] - mn);
                sfr[nf][2 * h] = e0;
                sfr[nf][2 * h + 1] = e1;
                rs += e0 + e1;
            }
            rs += __shfl_xor_sync(0xffffffffu, rs, 1);
            rs += __shfl_xor_sync(0xffffffffu, rs, 2);
            lsum[h] = lsum[h] * corr + rs;
#pragma unroll
            for (int nf = 0; nf < 16; nf++) {
                acc[nf][2 * h] *= corr;
                acc[nf][2 * h + 1] *= corr;
            }
        }

        // V(it) must be fully landed before PV
        if (pf) { CP_WAIT(2); } else { CP_WAIT(0); }

        // --- O += P V (P frags built from S frags) ---
#pragma unroll
        for (int j = 0; j < 4; j++) {
            uint32_t ph[4], pl[4];
#pragma unroll
            for (int q = 0; q < 4; q++) {
                const int nf = 2 * j + (q >> 1);
                const int rb = (q & 1) * 2;
                const float v0 = sfr[nf][rb], v1 = sfr[nf][rb + 1];
                const __nv_bfloat16 h0 = __float2bfloat16(v0);
                const __nv_bfloat16 h1 = __float2bfloat16(v1);
                ph[q] = pack_bf2(v0, v1);
                pl[q] = pack_bf2(v0 - __bfloat162float(h0), v1 - __bfloat162float(h1));
            }
#pragma unroll
            for (int t = 0; t < 8; t++) {
                uint32_t vh[4], vl[4];
                ldsm4t(vh, sVhi + v_off + j * 16 * FLP + t * 32);
                ldsm4t(vl, sVlo + v_off + j * 16 * FLP + t * 32);
                mma_bf16(acc[2 * t], ph, vh);
                mma_bf16(acc[2 * t], ph, vl);
                mma_bf16(acc[2 * t], pl, vh);
                mma_bf16(acc[2 * t + 1], ph, vh + 2);
                mma_bf16(acc[2 * t + 1], ph, vl + 2);
                mma_bf16(acc[2 * t + 1], pl, vh + 2);
            }
        }
    }

    // --- finalize: /l, split to bf16 hi/lo, store ---
#pragma unroll
    for (int h = 0; h < 2; h++) {
        const float inv = 1.0f / lsum[h];
        const int row = m0 + wid * 16 + (lane >> 2) + h * 8;
        const size_t base = (size_t)(b * LL + row) * 2048 + n * HDIM + 2 * (lane & 3);
#pragma unroll
        for (int nf = 0; nf < 16; nf++) {
            const float v0 = acc[nf][2 * h] * inv;
            const float v1 = acc[nf][2 * h + 1] * inv;
            const __nv_bfloat16 h0 = __float2bfloat16(v0);
            const __nv_bfloat16 h1 = __float2bfloat16(v1);
            *(uint32_t*)&g_ohi[base + nf * 8] = pack_bf2(v0, v1);
            *(uint32_t*)&g_olo[base + nf * 8] =
                pack_bf2(v0 - __bfloat162float(h0), v1 - __bfloat162float(h1));
        }
    }
}

// ---------------------------------------------------------------------------
// Launch
// ---------------------------------------------------------------------------
extern "C" void kernel_launch(void* const* d_in, const int* in_sizes, int n_in,
                              void* d_out, int out_size)
{
    const float* x   = (const float*)d_in[0];
    const int*   pos = (const int*)d_in[1];
    // d_in[2] = attn_mask (causal tril) — implied analytically, unused
    const float* wq  = (const float*)d_in[3];
    const float* wk  = (const float*)d_in[4];
    const float* wv  = (const float*)d_in[5];
    const float* wo  = (const float*)d_in[6];
    const float* qnw = (const float*)d_in[7];
    const float* knw = (const float*)d_in[8];
    float* out = (float*)d_out;

    cudaFuncSetAttribute(gemm_qkv_kernel,
                         cudaFuncAttributeMaxDynamicSharedMemorySize, GEMM_SMEM_BYTES);
    cudaFuncSetAttribute(gemm_out_kernel,
                         cudaFuncAttributeMaxDynamicSharedMemorySize, GEMM_SMEM_BYTES);
    cudaFuncSetAttribute(flash_kernel,
                         cudaFuncAttributeMaxDynamicSharedMemorySize, FL_SMEM);

    // 1. weights -> transposed bf16 hi/lo
    transpose_convert_kernel<<<dim3(64, 64), dim3(32, 8)>>>(wq, 2048, 2048, 0, 0);
    transpose_convert_kernel<<<dim3(32, 64), dim3(32, 8)>>>(wk, 2048, 1024, 2048, 0);
    transpose_convert_kernel<<<dim3(32, 64), dim3(32, 8)>>>(wv, 2048, 1024, 3072, 0);
    transpose_convert_kernel<<<dim3(64, 64), dim3(32, 8)>>>(wo, 2048, 2048, 0, 1);

    // 2. split X
    convert_split_x_kernel<<<(TOK * DD / 4 + 255) / 256, 256>>>(x);

    // 3. QKV projection (CTA tile 128x256, 512 threads)
    gemm_qkv_kernel<<<dim3(QKVW / 256, TOK / 128), 512, GEMM_SMEM_BYTES>>>();

    // 4. RMSNorm + RoPE + split (q,k,v)
    {
        const int nwarps = TOK * (NHEADS + 2 * KHEADS);   // 131072
        const int blocks = nwarps * 32 / 256;
        norm_rope_split_kernel<<<blocks, 256>>>(pos, qnw, knw);
    }

    // 5. Flash attention (tensor cores)
    flash_kernel<<<dim3(LL / 128, NHEADS, BB), 256, FL_SMEM>>>();

    // 6. output projection
    gemm_out_kernel<<<dim3(DD / 256, TOK / 128), 512, GEMM_SMEM_BYTES>>>(out);
}

// round 7
// speedup vs baseline: 1.1833x; 1.0505x over previous
#include <cuda_runtime.h>
#include <cuda_bf16.h>
#include <math.h>
#include <stdint.h>

// Problem constants
#define BB 2
#define LL 2048
#define DD 2048
#define NHEADS 16
#define KHEADS 8
#define HDIM 128
#define TOK (BB * LL)        // 4096
#define EPSV 1e-6f
#define QKVW 4096            // g_qkv row width (q:0..2047, k:2048..3071, v:3072..4095)

// ---------------------------------------------------------------------------
// Scratch (device globals — no runtime allocation allowed)
// ---------------------------------------------------------------------------
__device__ float g_qkv[(size_t)TOK * QKVW];                         // 67 MB
__device__ __align__(16) __nv_bfloat16 g_xhi[(size_t)TOK * DD];
__device__ __align__(16) __nv_bfloat16 g_xlo[(size_t)TOK * DD];
__device__ __align__(16) __nv_bfloat16 g_qhi[(size_t)TOK * DD];     // rope'd, pre-scaled q
__device__ __align__(16) __nv_bfloat16 g_qlo[(size_t)TOK * DD];
__device__ __align__(16) __nv_bfloat16 g_khi[(size_t)TOK * KHEADS * HDIM];
__device__ __align__(16) __nv_bfloat16 g_klo[(size_t)TOK * KHEADS * HDIM];
__device__ __align__(16) __nv_bfloat16 g_vhi[(size_t)TOK * KHEADS * HDIM];
__device__ __align__(16) __nv_bfloat16 g_vlo[(size_t)TOK * KHEADS * HDIM];
__device__ __align__(16) __nv_bfloat16 g_ohi[(size_t)TOK * DD];     // attention out
__device__ __align__(16) __nv_bfloat16 g_olo[(size_t)TOK * DD];
__device__ __align__(16) __nv_bfloat16 g_wthi[(size_t)QKVW * DD];   // [n][k] qkv weights
__device__ __align__(16) __nv_bfloat16 g_wtlo[(size_t)QKVW * DD];
__device__ __align__(16) __nv_bfloat16 g_wothi[(size_t)DD * DD];    // [n][k] wo
__device__ __align__(16) __nv_bfloat16 g_wotlo[(size_t)DD * DD];

extern __shared__ char dyn_smem[];

// ---------------------------------------------------------------------------
// PTX helpers (family-portable: cp.async / ldmatrix / mma.sync)
// ---------------------------------------------------------------------------
__device__ __forceinline__ uint32_t smem_u32(const void* p) {
    uint32_t a;
    asm("{ .reg .u64 t; cvta.to.shared.u64 t, %1; cvt.u32.u64 %0, t; }"
        : "=r"(a) : "l"(p));
    return a;
}

__device__ __forceinline__ void cp16(uint32_t dst, const void* src) {
    asm volatile("cp.async.cg.shared.global [%0], [%1], 16;" :: "r"(dst), "l"(src));
}
#define CP_COMMIT() asm volatile("cp.async.commit_group;" ::: "memory")
#define CP_WAIT(N)  asm volatile("cp.async.wait_group %0;" :: "n"(N) : "memory")

__device__ __forceinline__ void ldsm4(uint32_t* r, uint32_t a) {
    asm volatile("ldmatrix.sync.aligned.m8n8.x4.shared.b16 {%0,%1,%2,%3}, [%4];"
        : "=r"(r[0]), "=r"(r[1]), "=r"(r[2]), "=r"(r[3]) : "r"(a));
}
__device__ __forceinline__ void ldsm4t(uint32_t* r, uint32_t a) {
    asm volatile("ldmatrix.sync.aligned.m8n8.x4.trans.shared.b16 {%0,%1,%2,%3}, [%4];"
        : "=r"(r[0]), "=r"(r[1]), "=r"(r[2]), "=r"(r[3]) : "r"(a));
}

__device__ __forceinline__ void mma_bf16(float* c, const uint32_t* a, const uint32_t* b) {
    asm volatile(
        "mma.sync.aligned.m16n8k16.row.col.f32.bf16.bf16.f32 "
        "{%0,%1,%2,%3}, {%4,%5,%6,%7}, {%8,%9}, {%0,%1,%2,%3};"
        : "+f"(c[0]), "+f"(c[1]), "+f"(c[2]), "+f"(c[3])
        : "r"(a[0]), "r"(a[1]), "r"(a[2]), "r"(a[3]), "r"(b[0]), "r"(b[1]));
}

__device__ __forceinline__ uint32_t pack_bf2(float x, float y) {
    __nv_bfloat162 t;
    t.x = __float2bfloat16(x);
    t.y = __float2bfloat16(y);
    return *(uint32_t*)&t;
}

// ---------------------------------------------------------------------------
// Conversion kernels
// ---------------------------------------------------------------------------
__global__ void __launch_bounds__(256) transpose_convert_kernel(
    const float* __restrict__ src, int R, int C, int row_off, int which)
{
    __shared__ float t[32][33];
    const int c0 = blockIdx.x * 32;
    const int r0 = blockIdx.y * 32;
    const int tx = threadIdx.x;     // 0..31
    const int ty = threadIdx.y;     // 0..7

#pragma unroll
    for (int j = 0; j < 4; j++)
        t[ty + j * 8][tx] = src[(size_t)(r0 + ty + j * 8) * C + c0 + tx];
    __syncthreads();

    __nv_bfloat16* dhi = which ? g_wothi : g_wthi;
    __nv_bfloat16* dlo = which ? g_wotlo : g_wtlo;
#pragma unroll
    for (int j = 0; j < 4; j++) {
        const int i = ty + j * 8;
        const float v = t[tx][i];
        const __nv_bfloat16 h = __float2bfloat16(v);
        const __nv_bfloat16 l = __float2bfloat16(v - __bfloat162float(h));
        const size_t off = (size_t)(row_off + c0 + i) * DD + r0 + tx;
        dhi[off] = h;
        dlo[off] = l;
    }
}

__global__ void __launch_bounds__(256) convert_split_x_kernel(const float* __restrict__ src)
{
    const size_t i = (size_t)blockIdx.x * blockDim.x + threadIdx.x;
    const size_t n4 = (size_t)TOK * DD / 4;
    if (i >= n4) return;
    const float4 v = ((const float4*)src)[i];
    __nv_bfloat16 h0 = __float2bfloat16(v.x);
    __nv_bfloat16 h1 = __float2bfloat16(v.y);
    __nv_bfloat16 h2 = __float2bfloat16(v.z);
    __nv_bfloat16 h3 = __float2bfloat16(v.w);
    uint2 hp, lp;
    hp.x = pack_bf2(v.x, v.y);
    hp.y = pack_bf2(v.z, v.w);
    lp.x = pack_bf2(v.x - __bfloat162float(h0), v.y - __bfloat162float(h1));
    lp.y = pack_bf2(v.z - __bfloat162float(h2), v.w - __bfloat162float(h3));
    ((uint2*)g_xhi)[i] = hp;
    ((uint2*)g_xlo)[i] = lp;
}

// ---------------------------------------------------------------------------
// split-bf16 warp-MMA GEMM: C[M x N] = A[M x K] * B[N x K]^T, fp32 out
//   CTA tile 128x128, BK=32, 256 threads, 8 warps (2m x 4n), warp tile 64x32.
//   (R4's proven shape: 2 CTAs/SM for cross-CTA latency hiding.)
//   XOR-swizzled 64B row pitch (chunk' = c ^ ((row>>1)&3)) -> conflict-free
//   ldmatrix AND 32KB stages, so a 3-stage wait_group(1) ring fits 2 CTAs/SM.
//   3 products per frag: hi*hi + hi*lo + lo*hi (lo*lo dropped).
// ---------------------------------------------------------------------------
#define BK 32
#define PITCH 64
#define MAT_BYTES (128 * PITCH)           // 8192 per split
#define STAGE_BYTES (4 * MAT_BYTES)       // 32768
#define GEMM_SMEM_BYTES (3 * STAGE_BYTES) // 98304 (x2 CTAs = 196KB <= 227KB)

__device__ __forceinline__ uint32_t gswz(int r, int c) {
    // byte offset of 16B chunk c in row r under the XOR swizzle
    return (uint32_t)(r * PITCH + ((c ^ ((r >> 1) & 3)) << 4));
}

__device__ __forceinline__ void prefetch_stage(
    uint32_t sbase,
    const __nv_bfloat16* __restrict__ Ahi, const __nv_bfloat16* __restrict__ Alo,
    const __nv_bfloat16* __restrict__ Bhi, const __nv_bfloat16* __restrict__ Blo,
    int m0, int n0, int k0, int ldA, int ldB, int tid)
{
#pragma unroll
    for (int j = 0; j < 2; j++) {
        const int id = tid * 2 + j;          // 0..511
        const int r = id >> 2;               // row 0..127
        const int c = id & 3;                // 16B chunk 0..3
        const uint32_t soff = gswz(r, c);
        const size_t ga = (size_t)(m0 + r) * ldA + k0 + c * 8;
        const size_t gb = (size_t)(n0 + r) * ldB + k0 + c * 8;
        cp16(sbase + soff,                 Ahi + ga);
        cp16(sbase + MAT_BYTES + soff,     Alo + ga);
        cp16(sbase + 2 * MAT_BYTES + soff, Bhi + gb);
        cp16(sbase + 3 * MAT_BYTES + soff, Blo + gb);
    }
}

__device__ __forceinline__ void gemm_bf16x3_body(
    const __nv_bfloat16* __restrict__ Ahi, const __nv_bfloat16* __restrict__ Alo,
    const __nv_bfloat16* __restrict__ Bhi, const __nv_bfloat16* __restrict__ Blo,
    float* __restrict__ Cc, int K, int ldA, int ldB, int ldC)
{
    const int tid  = threadIdx.x;             // 256 threads
    const int lane = tid & 31;
    const int wid  = tid >> 5;                // 0..7
    const int wm   = wid & 1;                 // 2 m-warps
    const int wn   = wid >> 1;                // 4 n-warps
    const int m0   = blockIdx.y * 128;
    const int n0   = blockIdx.x * 128;
    const uint32_t smem_base = smem_u32(dyn_smem);

    float c[4][4][4];
#pragma unroll
    for (int i = 0; i < 4; i++)
#pragma unroll
        for (int j = 0; j < 4; j++)
#pragma unroll
            for (int k = 0; k < 4; k++) c[i][j][k] = 0.f;

    // ldmatrix lane addressing under the swizzle.
    // A: row = wm*64 + mf*16 + (lane&15); chunk = (lane>>4) + kf*2.
    //    (row>>1)&3 is invariant in mf (16-row steps), so swizzle is per-lane const.
    const int a_row  = wm * 64 + (lane & 15);
    const int a_swz  = (a_row >> 1) & 3;
    const uint32_t a_base = (uint32_t)(a_row * PITCH);
    const int a_c0   = lane >> 4;              // 0/1
    // B: row = wn*32 + (lane&7) + ((lane>>4)<<3); chunk = ((lane>>3)&1) + kf*2.
    const int b_row  = wn * 32 + (lane & 7) + ((lane >> 4) << 3);
    const int b_swz  = (b_row >> 1) & 3;
    const uint32_t b_base = (uint32_t)(b_row * PITCH);
    const int b_c0   = (lane >> 3) & 1;        // 0/1

    const int nk = K / BK;    // 64

    prefetch_stage(smem_base, Ahi, Alo, Bhi, Blo, m0, n0, 0, ldA, ldB, tid);
    CP_COMMIT();
    prefetch_stage(smem_base + STAGE_BYTES, Ahi, Alo, Bhi, Blo, m0, n0, BK, ldA, ldB, tid);
    CP_COMMIT();

    int slot = 0;
    for (int it = 0; it < nk; it++) {
        if (it < nk - 1) { CP_WAIT(1); } else { CP_WAIT(0); }
        __syncthreads();   // all warps done reading the slot we're about to refill

        if (it + 2 < nk) {
            int ps = slot + 2;
            if (ps >= 3) ps -= 3;
            prefetch_stage(smem_base + ps * STAGE_BYTES,
                           Ahi, Alo, Bhi, Blo, m0, n0, (it + 2) * BK, ldA, ldB, tid);
            CP_COMMIT();
        }

        const uint32_t sA = smem_base + slot * STAGE_BYTES;
        const uint32_t sB = sA + 2 * MAT_BYTES;

#pragma unroll
        for (int kf = 0; kf < 2; kf++) {
            uint32_t a[2][4][4];   // [split][mf][reg]
            uint32_t b[2][2][4];   // [split][nf2][reg]
            const uint32_t a_coff = (uint32_t)(((a_c0 + kf * 2) ^ a_swz) << 4);
            const uint32_t b_coff = (uint32_t)(((b_c0 + kf * 2) ^ b_swz) << 4);
#pragma unroll
            for (int mf = 0; mf < 4; mf++) {
                const uint32_t ad = sA + a_base + mf * (16 * PITCH) + a_coff;
                ldsm4(a[0][mf], ad);
                ldsm4(a[1][mf], ad + MAT_BYTES);
            }
#pragma unroll
            for (int nf2 = 0; nf2 < 2; nf2++) {
                const uint32_t bd = sB + b_base + nf2 * (16 * PITCH) + b_coff;
                ldsm4(b[0][nf2], bd);
                ldsm4(b[1][nf2], bd + MAT_BYTES);
            }
#pragma unroll
            for (int mf = 0; mf < 4; mf++)
#pragma unroll
                for (int nf = 0; nf < 4; nf++) {
                    float* cc = c[mf][nf];
                    const uint32_t* bh = &b[0][nf >> 1][(nf & 1) * 2];
                    const uint32_t* bl = &b[1][nf >> 1][(nf & 1) * 2];
                    mma_bf16(cc, a[0][mf], bh);   // hi*hi
                    mma_bf16(cc, a[0][mf], bl);   // hi*lo
                    mma_bf16(cc, a[1][mf], bh);   // lo*hi
                }
        }

        if (++slot == 3) slot = 0;
    }

    const int row0 = m0 + wm * 64;
    const int col0 = n0 + wn * 32;
    const int gr = lane >> 2;
    const int gc = (lane & 3) * 2;
#pragma unroll
    for (int mf = 0; mf < 4; mf++)
#pragma unroll
        for (int nf = 0; nf < 4; nf++) {
            float* cc = c[mf][nf];
            const int r = row0 + mf * 16 + gr;
            const int cl = col0 + nf * 8 + gc;
            *(float2*)&Cc[(size_t)r * ldC + cl]       = make_float2(cc[0], cc[1]);
            *(float2*)&Cc[(size_t)(r + 8) * ldC + cl] = make_float2(cc[2], cc[3]);
        }
}

__global__ void __launch_bounds__(256, 2) gemm_qkv_kernel() {
    gemm_bf16x3_body(g_xhi, g_xlo, g_wthi, g_wtlo, g_qkv, DD, DD, DD, QKVW);
}
__global__ void __launch_bounds__(256, 2) gemm_out_kernel(float* __restrict__ out) {
    gemm_bf16x3_body(g_ohi, g_olo, g_wothi, g_wotlo, out, DD, DD, DD, DD);
}

// ---------------------------------------------------------------------------
// RMSNorm + RoPE + bf16 hi/lo split. One warp per 128-vector.
// ---------------------------------------------------------------------------
__global__ void __launch_bounds__(256) norm_rope_split_kernel(
    const int* __restrict__ pos_ids,
    const float* __restrict__ q_norm_w,
    const float* __restrict__ k_norm_w)
{
    const int warp = (blockIdx.x * blockDim.x + threadIdx.x) >> 5;
    const int lane = threadIdx.x & 31;
    const int NQ = TOK * NHEADS;
    const int NK = TOK * KHEADS;

    // --- V path: straight split, no norm/rope ---
    if (warp >= NQ + NK) {
        const int idx = warp - NQ - NK;
        if (idx >= TOK * KHEADS) return;
        const int token = idx >> 3;
        const int kh = idx & 7;
        const float* src = g_qkv + (size_t)token * QKVW + 3072 + kh * HDIM + lane * 4;
        const float4 v = *(const float4*)src;
        __nv_bfloat16 h0 = __float2bfloat16(v.x);
        __nv_bfloat16 h1 = __float2bfloat16(v.y);
        __nv_bfloat16 h2 = __float2bfloat16(v.z);
        __nv_bfloat16 h3 = __float2bfloat16(v.w);
        uint2 hp, lp;
        hp.x = pack_bf2(v.x, v.y);
        hp.y = pack_bf2(v.z, v.w);
        lp.x = pack_bf2(v.x - __bfloat162float(h0), v.y - __bfloat162float(h1));
        lp.y = pack_bf2(v.z - __bfloat162float(h2), v.w - __bfloat162float(h3));
        const size_t off = (size_t)token * 1024 + kh * HDIM + lane * 4;
        *(uint2*)&g_vhi[off] = hp;
        *(uint2*)&g_vlo[off] = lp;
        return;
    }

    const bool isq = warp < NQ;
    int token, hidx;
    const float* vecsrc;
    const float* w;
    if (isq) {
        token = warp >> 4;
        hidx = warp & 15;
        vecsrc = g_qkv + (size_t)token * QKVW + hidx * HDIM;
        w = q_norm_w;
    } else {
        const int kv = warp - NQ;
        token = kv >> 3;
        hidx = kv & 7;
        vecsrc = g_qkv + (size_t)token * QKVW + 2048 + hidx * HDIM;
        w = k_norm_w;
    }
    const int pos = pos_ids[token];

    float4 x4 = *(const float4*)&vecsrc[lane * 4];
    float ss = x4.x * x4.x + x4.y * x4.y + x4.z * x4.z + x4.w * x4.w;
#pragma unroll
    for (int m = 16; m; m >>= 1) ss += __shfl_xor_sync(0xffffffffu, ss, m);
    const float rinv = rsqrtf(ss * (1.0f / HDIM) + EPSV);

    float4 w4 = *(const float4*)&w[lane * 4];
    float n0 = x4.x * w4.x * rinv;
    float n1 = x4.y * w4.y * rinv;
    float n2 = x4.z * w4.z * rinv;
    float n3 = x4.w * w4.w * rinv;

    float p0 = __shfl_xor_sync(0xffffffffu, n0, 16);
    float p1 = __shfl_xor_sync(0xffffffffu, n1, 16);
    float p2 = __shfl_xor_sync(0xffffffffu, n2, 16);
    float p3 = __shfl_xor_sync(0xffffffffu, n3, 16);

    const bool firsthalf = lane < 16;
    const int pbase = (lane & 15) * 4;
    const float fpos = (float)pos;
    const double L2T = 19.931568569324174;   // log2(1e6)
    const float QS = isq ? 0.08838834764831845f * 1.4426950408889634f : 1.0f;

    float nv[4] = {n0, n1, n2, n3};
    float pv[4] = {p0, p1, p2, p3};
    float res[4];
#pragma unroll
    for (int j = 0; j < 4; j++) {
        const int p = pbase + j;
        const float inv_ts = exp2f((float)(-(double)p * L2T / 64.0));
        const float ang = fpos * inv_ts;
        float sv, cv;
        sincosf(ang, &sv, &cv);
        const float r = firsthalf ? (nv[j] * cv - pv[j] * sv)
                                  : (nv[j] * cv + pv[j] * sv);
        res[j] = r * QS;
    }

    __nv_bfloat16 h0 = __float2bfloat16(res[0]);
    __nv_bfloat16 h1 = __float2bfloat16(res[1]);
    __nv_bfloat16 h2 = __float2bfloat16(res[2]);
    __nv_bfloat16 h3 = __float2bfloat16(res[3]);
    uint2 hp, lp;
    hp.x = pack_bf2(res[0], res[1]);
    hp.y = pack_bf2(res[2], res[3]);
    lp.x = pack_bf2(res[0] - __bfloat162float(h0), res[1] - __bfloat162float(h1));
    lp.y = pack_bf2(res[2] - __bfloat162float(h2), res[3] - __bfloat162float(h3));

    if (isq) {
        const size_t off = (size_t)token * 2048 + hidx * HDIM + lane * 4;
        *(uint2*)&g_qhi[off] = hp;
        *(uint2*)&g_qlo[off] = lp;
    } else {
        const size_t off = (size_t)token * 1024 + hidx * HDIM + lane * 4;
        *(uint2*)&g_khi[off] = hp;
        *(uint2*)&g_klo[off] = lp;
    }
}

// ---------------------------------------------------------------------------
// Flash attention on tensor cores (mma.sync bf16, split x3).
//   Block: 128 q-rows x (head n, batch b). 8 warps, warp = 16 q-rows.
//   KV tiles of 64, double-buffered cp.async with SPLIT K/V commit groups
//   so the V transfer overlaps the S=QK^T compute.
// ---------------------------------------------------------------------------
#define FLP 272
#define FL_QSZ (128 * FLP)          // 34816
#define FL_KVSZ (64 * FLP)          // 17408
#define FL_STAGE (4 * FL_KVSZ)      // 69632
#define FL_SMEM (2 * FL_QSZ + 2 * FL_STAGE)   // 208896

__device__ __forceinline__ void fl_prefetch_k(
    uint32_t sbase, int b, int kvh, int kv0, int tid)
{
#pragma unroll
    for (int u = 0; u < 8; u++) {
        const int mtx = u >> 2;                      // 0:Khi 1:Klo
        const int row = ((u & 3) << 4) + (tid >> 4); // 0..63
        const int ch = tid & 15;
        const __nv_bfloat16* g = (mtx ? g_klo : g_khi) +
            (size_t)(b * LL + kv0 + row) * 1024 + kvh * HDIM + ch * 8;
        cp16(sbase + mtx * FL_KVSZ + row * FLP + ch * 16, g);
    }
}
__device__ __forceinline__ void fl_prefetch_v(
    uint32_t sbase, int b, int kvh, int kv0, int tid)
{
#pragma unroll
    for (int u = 0; u < 8; u++) {
        const int mtx = u >> 2;                      // 0:Vhi 1:Vlo
        const int row = ((u & 3) << 4) + (tid >> 4);
        const int ch = tid & 15;
        const __nv_bfloat16* g = (mtx ? g_vlo : g_vhi) +
            (size_t)(b * LL + kv0 + row) * 1024 + kvh * HDIM + ch * 8;
        cp16(sbase + (2 + mtx) * FL_KVSZ + row * FLP + ch * 16, g);
    }
}

__global__ void __launch_bounds__(256, 1) flash_kernel()
{
    const int tid = threadIdx.x;
    const int lane = tid & 31;
    const int wid = tid >> 5;
    const int b = blockIdx.z;
    const int n = blockIdx.y;
    const int mt = (int)gridDim.x - 1 - (int)blockIdx.x;  // big tiles launch first
    const int kvh = n >> 1;
    const int m0 = mt * 128;

    const uint32_t sb = smem_u32(dyn_smem);
    const uint32_t sQhi = sb;
    const uint32_t sQlo = sb + FL_QSZ;
    const uint32_t sStage0 = sb + 2 * FL_QSZ;

    // load Q hi/lo + K0 (group 1), V0 (group 2)
#pragma unroll
    for (int u = 0; u < 16; u++) {
        const int mtx = u >> 3;
        const int row = ((u & 7) << 4) + (tid >> 4);
        const int ch = tid & 15;
        const __nv_bfloat16* g = (mtx ? g_qlo : g_qhi) +
            (size_t)(b * LL + m0 + row) * 2048 + n * HDIM + ch * 8;
        cp16((mtx ? sQlo : sQhi) + row * FLP + ch * 16, g);
    }
    fl_prefetch_k(sStage0, b, kvh, 0, tid);
    CP_COMMIT();
    fl_prefetch_v(sStage0, b, kvh, 0, tid);
    CP_COMMIT();

    float acc[16][4];
#pragma unroll
    for (int i = 0; i < 16; i++)
#pragma unroll
        for (int j = 0; j < 4; j++) acc[i][j] = 0.f;
    float m2[2] = {-1e30f, -1e30f};
    float lsum[2] = {0.f, 0.f};

    const uint32_t a_off = (uint32_t)((wid * 16 + (lane & 15)) * FLP + (lane >> 4) * 16);
    const uint32_t bk_off = (uint32_t)(((lane & 7) + ((lane >> 4) << 3)) * FLP +
                                       ((lane >> 3) & 1) * 16);
    const uint32_t v_off = (uint32_t)(((lane & 7) + ((lane >> 3) & 1) * 8) * FLP +
                                      (lane >> 4) * 16);

    const int nkv = 2 * (mt + 1);
    for (int it = 0; it < nkv; it++) {
        CP_WAIT(1);        // K(it) (+Q on it=0) landed; V(it) may be in flight
        __syncthreads();   // everyone done reading the slot we're about to refill
        const bool pf = (it + 1 < nkv);
        if (pf) {
            const uint32_t ns = sStage0 + ((it + 1) & 1) * FL_STAGE;
            fl_prefetch_k(ns, b, kvh, (it + 1) * 64, tid);
            CP_COMMIT();
            fl_prefetch_v(ns, b, kvh, (it + 1) * 64, tid);
            CP_COMMIT();
        }
        const uint32_t sKhi = sStage0 + (it & 1) * FL_STAGE;
        const uint32_t sKlo = sKhi + FL_KVSZ;
        const uint32_t sVhi = sKhi + 2 * FL_KVSZ;
        const uint32_t sVlo = sKhi + 3 * FL_KVSZ;

        // --- S = Q K^T (scores in exp2 domain; q pre-scaled) ---
        float sfr[8][4];
#pragma unroll
        for (int i = 0; i < 8; i++)
#pragma unroll
            for (int j = 0; j < 4; j++) sfr[i][j] = 0.f;

#pragma unroll
        for (int kf = 0; kf < 8; kf++) {
            uint32_t ah[4], al[4];
            ldsm4(ah, sQhi + a_off + kf * 32);
            ldsm4(al, sQlo + a_off + kf * 32);
#pragma unroll
            for (int p2 = 0; p2 < 4; p2++) {
                uint32_t bh[4], bl[4];
                ldsm4(bh, sKhi + bk_off + p2 * 16 * FLP + kf * 32);
                ldsm4(bl, sKlo + bk_off + p2 * 16 * FLP + kf * 32);
                mma_bf16(sfr[2 * p2], ah, bh);
                mma_bf16(sfr[2 * p2], ah, bl);
                mma_bf16(sfr[2 * p2], al, bh);
                mma_bf16(sfr[2 * p2 + 1], ah, bh + 2);
                mma_bf16(sfr[2 * p2 + 1], ah, bl + 2);
                mma_bf16(sfr[2 * p2 + 1], al, bh + 2);
            }
        }

        // --- causal mask (only near-diagonal tiles) ---
        const int rbase = m0 + wid * 16 + (lane >> 2);
        if (it * 64 + 63 > m0 + wid * 16) {
#pragma unroll
            for (int nf = 0; nf < 8; nf++) {
                const int cg = it * 64 + nf * 8 + 2 * (lane & 3);
#pragma unroll
                for (int rg = 0; rg < 4; rg++) {
                    const int row = rbase + (rg >> 1) * 8;
                    const int col = cg + (rg & 1);
                    if (col > row) sfr[nf][rg] = -1e30f;
                }
            }
        }

        // --- online softmax (exp2 domain), warp-local rows ---
#pragma unroll
        for (int h = 0; h < 2; h++) {
            float tm = -1e30f;
#pragma unroll
            for (int nf = 0; nf < 8; nf++)
                tm = fmaxf(tm, fmaxf(sfr[nf][2 * h], sfr[nf][2 * h + 1]));
            tm = fmaxf(tm, __shfl_xor_sync(0xffffffffu, tm, 1));
            tm = fmaxf(tm, __shfl_xor_sync(0xffffffffu, tm, 2));
            const float mn = fmaxf(m2[h], tm);
            const float corr = exp2f(m2[h] - mn);
            m2[h] = mn;
            float rs = 0.f;
#pragma unroll
            for (int nf = 0; nf < 8; nf++) {
                const float e0 = exp2f(sfr[nf][2 * h] - mn);
                const float e1 = exp2f(sfr[nf][2 * h + 1] - mn);
                sfr[nf][2 * h] = e0;
                sfr[nf][2 * h + 1] = e1;
                rs += e0 + e1;
            }
            rs += __shfl_xor_sync(0xffffffffu, rs, 1);
            rs += __shfl_xor_sync(0xffffffffu, rs, 2);
            lsum[h] = lsum[h] * corr + rs;
#pragma unroll
            for (int nf = 0; nf < 16; nf++) {
                acc[nf][2 * h] *= corr;
                acc[nf][2 * h + 1] *= corr;
            }
        }

        // V(it) must be fully landed before PV
        if (pf) { CP_WAIT(2); } else { CP_WAIT(0); }

        // --- O += P V (P frags built from S frags) ---
#pragma unroll
        for (int j = 0; j < 4; j++) {
            uint32_t ph[4], pl[4];
#pragma unroll
            for (int q = 0; q < 4; q++) {
                const int nf = 2 * j + (q >> 1);
                const int rb = (q & 1) * 2;
                const float v0 = sfr[nf][rb], v1 = sfr[nf][rb + 1];
                const __nv_bfloat16 h0 = __float2bfloat16(v0);
                const __nv_bfloat16 h1 = __float2bfloat16(v1);
                ph[q] = pack_bf2(v0, v1);
                pl[q] = pack_bf2(v0 - __bfloat162float(h0), v1 - __bfloat162float(h1));
            }
#pragma unroll
            for (int t = 0; t < 8; t++) {
                uint32_t vh[4], vl[4];
                ldsm4t(vh, sVhi + v_off + j * 16 * FLP + t * 32);
                ldsm4t(vl, sVlo + v_off + j * 16 * FLP + t * 32);
                mma_bf16(acc[2 * t], ph, vh);
                mma_bf16(acc[2 * t], ph, vl);
                mma_bf16(acc[2 * t], pl, vh);
                mma_bf16(acc[2 * t + 1], ph, vh + 2);
                mma_bf16(acc[2 * t + 1], ph, vl + 2);
                mma_bf16(acc[2 * t + 1], pl, vh + 2);
            }
        }
    }

    // --- finalize: /l, split to bf16 hi/lo, store ---
#pragma unroll
    for (int h = 0; h < 2; h++) {
        const float inv = 1.0f / lsum[h];
        const int row = m0 + wid * 16 + (lane >> 2) + h * 8;
        const size_t base = (size_t)(b * LL + row) * 2048 + n * HDIM + 2 * (lane & 3);
#pragma unroll
        for (int nf = 0; nf < 16; nf++) {
            const float v0 = acc[nf][2 * h] * inv;
            const float v1 = acc[nf][2 * h + 1] * inv;
            const __nv_bfloat16 h0 = __float2bfloat16(v0);
            const __nv_bfloat16 h1 = __float2bfloat16(v1);
            *(uint32_t*)&g_ohi[base + nf * 8] = pack_bf2(v0, v1);
            *(uint32_t*)&g_olo[base + nf * 8] =
                pack_bf2(v0 - __bfloat162float(h0), v1 - __bfloat162float(h1));
        }
    }
}

// ---------------------------------------------------------------------------
// Launch
// ---------------------------------------------------------------------------
extern "C" void kernel_launch(void* const* d_in, const int* in_sizes, int n_in,
                              void* d_out, int out_size)
{
    const float* x   = (const float*)d_in[0];
    const int*   pos = (const int*)d_in[1];
    // d_in[2] = attn_mask (causal tril) — implied analytically, unused
    const float* wq  = (const float*)d_in[3];
    const float* wk  = (const float*)d_in[4];
    const float* wv  = (const float*)d_in[5];
    const float* wo  = (const float*)d_in[6];
    const float* qnw = (const float*)d_in[7];
    const float* knw = (const float*)d_in[8];
    float* out = (float*)d_out;

    cudaFuncSetAttribute(gemm_qkv_kernel,
                         cudaFuncAttributeMaxDynamicSharedMemorySize, GEMM_SMEM_BYTES);
    cudaFuncSetAttribute(gemm_out_kernel,
                         cudaFuncAttributeMaxDynamicSharedMemorySize, GEMM_SMEM_BYTES);
    cudaFuncSetAttribute(flash_kernel,
                         cudaFuncAttributeMaxDynamicSharedMemorySize, FL_SMEM);

    // 1. weights -> transposed bf16 hi/lo
    transpose_convert_kernel<<<dim3(64, 64), dim3(32, 8)>>>(wq, 2048, 2048, 0, 0);
    transpose_convert_kernel<<<dim3(32, 64), dim3(32, 8)>>>(wk, 2048, 1024, 2048, 0);
    transpose_convert_kernel<<<dim3(32, 64), dim3(32, 8)>>>(wv, 2048, 1024, 3072, 0);
    transpose_convert_kernel<<<dim3(64, 64), dim3(32, 8)>>>(wo, 2048, 2048, 0, 1);

    // 2. split X
    convert_split_x_kernel<<<(TOK * DD / 4 + 255) / 256, 256>>>(x);

    // 3. QKV projection (CTA tile 128x128, 2 CTAs/SM, 3-stage ring)
    gemm_qkv_kernel<<<dim3(QKVW / 128, TOK / 128), 256, GEMM_SMEM_BYTES>>>();

    // 4. RMSNorm + RoPE + split (q,k,v)
    {
        const int nwarps = TOK * (NHEADS + 2 * KHEADS);   // 131072
        const int blocks = nwarps * 32 / 256;
        norm_rope_split_kernel<<<blocks, 256>>>(pos, qnw, knw);
    }

    // 5. Flash attention (tensor cores)
    flash_kernel<<<dim3(LL / 128, NHEADS, BB), 256, FL_SMEM>>>();

    // 6. output projection
    gemm_out_kernel<<<dim3(DD / 128, TOK / 128), 256, GEMM_SMEM_BYTES>>>(out);
}

// round 8
// speedup vs baseline: 1.1961x; 1.0108x over previous
#include <cuda_runtime.h>
#include <cuda_bf16.h>
#include <math.h>
#include <stdint.h>

// Problem constants
#define BB 2
#define LL 2048
#define DD 2048
#define NHEADS 16
#define KHEADS 8
#define HDIM 128
#define TOK (BB * LL)        // 4096
#define EPSV 1e-6f
#define QKVW 4096            // g_qkv row width (q:0..2047, k:2048..3071, v:3072..4095)

// ---------------------------------------------------------------------------
// Scratch (device globals — no runtime allocation allowed)
// ---------------------------------------------------------------------------
__device__ float g_qkv[(size_t)TOK * QKVW];                         // 67 MB
__device__ __align__(16) __nv_bfloat16 g_xhi[(size_t)TOK * DD];
__device__ __align__(16) __nv_bfloat16 g_xlo[(size_t)TOK * DD];
__device__ __align__(16) __nv_bfloat16 g_qhi[(size_t)TOK * DD];     // rope'd, pre-scaled q
__device__ __align__(16) __nv_bfloat16 g_qlo[(size_t)TOK * DD];
__device__ __align__(16) __nv_bfloat16 g_khi[(size_t)TOK * KHEADS * HDIM];
__device__ __align__(16) __nv_bfloat16 g_klo[(size_t)TOK * KHEADS * HDIM];
__device__ __align__(16) __nv_bfloat16 g_vhi[(size_t)TOK * KHEADS * HDIM];
__device__ __align__(16) __nv_bfloat16 g_vlo[(size_t)TOK * KHEADS * HDIM];
__device__ __align__(16) __nv_bfloat16 g_ohi[(size_t)TOK * DD];     // attention out
__device__ __align__(16) __nv_bfloat16 g_olo[(size_t)TOK * DD];
__device__ __align__(16) __nv_bfloat16 g_wthi[(size_t)QKVW * DD];   // [n][k] qkv weights
__device__ __align__(16) __nv_bfloat16 g_wtlo[(size_t)QKVW * DD];
__device__ __align__(16) __nv_bfloat16 g_wothi[(size_t)DD * DD];    // [n][k] wo
__device__ __align__(16) __nv_bfloat16 g_wotlo[(size_t)DD * DD];

extern __shared__ char dyn_smem[];

// ---------------------------------------------------------------------------
// PTX helpers (family-portable: cp.async / ldmatrix / mma.sync)
// ---------------------------------------------------------------------------
__device__ __forceinline__ uint32_t smem_u32(const void* p) {
    uint32_t a;
    asm("{ .reg .u64 t; cvta.to.shared.u64 t, %1; cvt.u32.u64 %0, t; }"
        : "=r"(a) : "l"(p));
    return a;
}

__device__ __forceinline__ void cp16(uint32_t dst, const void* src) {
    asm volatile("cp.async.cg.shared.global [%0], [%1], 16;" :: "r"(dst), "l"(src));
}
#define CP_COMMIT() asm volatile("cp.async.commit_group;" ::: "memory")
#define CP_WAIT(N)  asm volatile("cp.async.wait_group %0;" :: "n"(N) : "memory")

__device__ __forceinline__ void ldsm4(uint32_t* r, uint32_t a) {
    asm volatile("ldmatrix.sync.aligned.m8n8.x4.shared.b16 {%0,%1,%2,%3}, [%4];"
        : "=r"(r[0]), "=r"(r[1]), "=r"(r[2]), "=r"(r[3]) : "r"(a));
}
__device__ __forceinline__ void ldsm4t(uint32_t* r, uint32_t a) {
    asm volatile("ldmatrix.sync.aligned.m8n8.x4.trans.shared.b16 {%0,%1,%2,%3}, [%4];"
        : "=r"(r[0]), "=r"(r[1]), "=r"(r[2]), "=r"(r[3]) : "r"(a));
}

__device__ __forceinline__ void mma_bf16(float* c, const uint32_t* a, const uint32_t* b) {
    asm volatile(
        "mma.sync.aligned.m16n8k16.row.col.f32.bf16.bf16.f32 "
        "{%0,%1,%2,%3}, {%4,%5,%6,%7}, {%8,%9}, {%0,%1,%2,%3};"
        : "+f"(c[0]), "+f"(c[1]), "+f"(c[2]), "+f"(c[3])
        : "r"(a[0]), "r"(a[1]), "r"(a[2]), "r"(a[3]), "r"(b[0]), "r"(b[1]));
}

__device__ __forceinline__ uint32_t pack_bf2(float x, float y) {
    __nv_bfloat162 t;
    t.x = __float2bfloat16(x);
    t.y = __float2bfloat16(y);
    return *(uint32_t*)&t;
}

// ---------------------------------------------------------------------------
// Conversion kernels
// ---------------------------------------------------------------------------
// All four weight transposes in one launch (grid.z selects the matrix).
__global__ void __launch_bounds__(256) transpose_convert_all_kernel(
    const float* __restrict__ wq, const float* __restrict__ wk,
    const float* __restrict__ wv, const float* __restrict__ wo)
{
    const int z = blockIdx.z;
    const float* src;
    int C, row_off;
    __nv_bfloat16 *dhi, *dlo;
    if (z == 0)      { src = wq; C = 2048; row_off = 0;    dhi = g_wthi;  dlo = g_wtlo;  }
    else if (z == 1) { if (blockIdx.x >= 32) return;
                       src = wk; C = 1024; row_off = 2048; dhi = g_wthi;  dlo = g_wtlo;  }
    else if (z == 2) { if (blockIdx.x >= 32) return;
                       src = wv; C = 1024; row_off = 3072; dhi = g_wthi;  dlo = g_wtlo;  }
    else             { src = wo; C = 2048; row_off = 0;    dhi = g_wothi; dlo = g_wotlo; }

    __shared__ float t[32][33];
    const int c0 = blockIdx.x * 32;
    const int r0 = blockIdx.y * 32;
    const int tx = threadIdx.x;     // 0..31
    const int ty = threadIdx.y;     // 0..7

#pragma unroll
    for (int j = 0; j < 4; j++)
        t[ty + j * 8][tx] = src[(size_t)(r0 + ty + j * 8) * C + c0 + tx];
    __syncthreads();

#pragma unroll
    for (int j = 0; j < 4; j++) {
        const int i = ty + j * 8;
        const float v = t[tx][i];
        const __nv_bfloat16 h = __float2bfloat16(v);
        const __nv_bfloat16 l = __float2bfloat16(v - __bfloat162float(h));
        const size_t off = (size_t)(row_off + c0 + i) * DD + r0 + tx;
        dhi[off] = h;
        dlo[off] = l;
    }
}

__global__ void __launch_bounds__(256) convert_split_x_kernel(const float* __restrict__ src)
{
    const size_t i = (size_t)blockIdx.x * blockDim.x + threadIdx.x;
    const size_t n4 = (size_t)TOK * DD / 4;
    if (i >= n4) return;
    const float4 v = ((const float4*)src)[i];
    __nv_bfloat16 h0 = __float2bfloat16(v.x);
    __nv_bfloat16 h1 = __float2bfloat16(v.y);
    __nv_bfloat16 h2 = __float2bfloat16(v.z);
    __nv_bfloat16 h3 = __float2bfloat16(v.w);
    uint2 hp, lp;
    hp.x = pack_bf2(v.x, v.y);
    hp.y = pack_bf2(v.z, v.w);
    lp.x = pack_bf2(v.x - __bfloat162float(h0), v.y - __bfloat162float(h1));
    lp.y = pack_bf2(v.z - __bfloat162float(h2), v.w - __bfloat162float(h3));
    ((uint2*)g_xhi)[i] = hp;
    ((uint2*)g_xlo)[i] = lp;
}

// ---------------------------------------------------------------------------
// split-bf16 warp-MMA GEMM: C[M x N] = A[M x K] * B[N x K]^T, fp32 out
//   CTA tile 128x128, BK=32, 256 threads, 8 warps (2m x 4n), warp tile 64x32.
//   XOR-swizzled 64B pitch, 3-stage cp.async ring, 2 CTAs/SM.
//   R8: product-major MMA ordering (hh x4nf, hl x4nf, lh x4nf per mf) —
//   RAW distance on accumulators 1 -> 4; A-frags per-mf transient (reg relief).
// ---------------------------------------------------------------------------
#define BK 32
#define PITCH 64
#define MAT_BYTES (128 * PITCH)           // 8192 per split
#define STAGE_BYTES (4 * MAT_BYTES)       // 32768
#define GEMM_SMEM_BYTES (3 * STAGE_BYTES) // 98304 (x2 CTAs = 196KB <= 227KB)

__device__ __forceinline__ uint32_t gswz(int r, int c) {
    return (uint32_t)(r * PITCH + ((c ^ ((r >> 1) & 3)) << 4));
}

__device__ __forceinline__ void prefetch_stage(
    uint32_t sbase,
    const __nv_bfloat16* __restrict__ Ahi, const __nv_bfloat16* __restrict__ Alo,
    const __nv_bfloat16* __restrict__ Bhi, const __nv_bfloat16* __restrict__ Blo,
    int m0, int n0, int k0, int ldA, int ldB, int tid)
{
#pragma unroll
    for (int j = 0; j < 2; j++) {
        const int id = tid * 2 + j;          // 0..511
        const int r = id >> 2;               // row 0..127
        const int c = id & 3;                // 16B chunk 0..3
        const uint32_t soff = gswz(r, c);
        const size_t ga = (size_t)(m0 + r) * ldA + k0 + c * 8;
        const size_t gb = (size_t)(n0 + r) * ldB + k0 + c * 8;
        cp16(sbase + soff,                 Ahi + ga);
        cp16(sbase + MAT_BYTES + soff,     Alo + ga);
        cp16(sbase + 2 * MAT_BYTES + soff, Bhi + gb);
        cp16(sbase + 3 * MAT_BYTES + soff, Blo + gb);
    }
}

__device__ __forceinline__ void gemm_bf16x3_body(
    const __nv_bfloat16* __restrict__ Ahi, const __nv_bfloat16* __restrict__ Alo,
    const __nv_bfloat16* __restrict__ Bhi, const __nv_bfloat16* __restrict__ Blo,
    float* __restrict__ Cc, int K, int ldA, int ldB, int ldC)
{
    const int tid  = threadIdx.x;             // 256 threads
    const int lane = tid & 31;
    const int wid  = tid >> 5;                // 0..7
    const int wm   = wid & 1;                 // 2 m-warps
    const int wn   = wid >> 1;                // 4 n-warps
    const int m0   = blockIdx.y * 128;
    const int n0   = blockIdx.x * 128;
    const uint32_t smem_base = smem_u32(dyn_smem);

    float c[4][4][4];
#pragma unroll
    for (int i = 0; i < 4; i++)
#pragma unroll
        for (int j = 0; j < 4; j++)
#pragma unroll
            for (int k = 0; k < 4; k++) c[i][j][k] = 0.f;

    const int a_row  = wm * 64 + (lane & 15);
    const int a_swz  = (a_row >> 1) & 3;
    const uint32_t a_base = (uint32_t)(a_row * PITCH);
    const int a_c0   = lane >> 4;              // 0/1
    const int b_row  = wn * 32 + (lane & 7) + ((lane >> 4) << 3);
    const int b_swz  = (b_row >> 1) & 3;
    const uint32_t b_base = (uint32_t)(b_row * PITCH);
    const int b_c0   = (lane >> 3) & 1;        // 0/1

    const int nk = K / BK;    // 64

    prefetch_stage(smem_base, Ahi, Alo, Bhi, Blo, m0, n0, 0, ldA, ldB, tid);
    CP_COMMIT();
    prefetch_stage(smem_base + STAGE_BYTES, Ahi, Alo, Bhi, Blo, m0, n0, BK, ldA, ldB, tid);
    CP_COMMIT();

    int slot = 0;
    for (int it = 0; it < nk; it++) {
        if (it < nk - 1) { CP_WAIT(1); } else { CP_WAIT(0); }
        __syncthreads();

        if (it + 2 < nk) {
            int ps = slot + 2;
            if (ps >= 3) ps -= 3;
            prefetch_stage(smem_base + ps * STAGE_BYTES,
                           Ahi, Alo, Bhi, Blo, m0, n0, (it + 2) * BK, ldA, ldB, tid);
            CP_COMMIT();
        }

        const uint32_t sA = smem_base + slot * STAGE_BYTES;
        const uint32_t sB = sA + 2 * MAT_BYTES;

#pragma unroll
        for (int kf = 0; kf < 2; kf++) {
            uint32_t b[2][2][4];   // [split][nf2][reg]
            const uint32_t a_coff = (uint32_t)(((a_c0 + kf * 2) ^ a_swz) << 4);
            const uint32_t b_coff = (uint32_t)(((b_c0 + kf * 2) ^ b_swz) << 4);
#pragma unroll
            for (int nf2 = 0; nf2 < 2; nf2++) {
                const uint32_t bd = sB + b_base + nf2 * (16 * PITCH) + b_coff;
                ldsm4(b[0][nf2], bd);
                ldsm4(b[1][nf2], bd + MAT_BYTES);
            }
#pragma unroll
            for (int mf = 0; mf < 4; mf++) {
                uint32_t ah[4], al[4];
                const uint32_t ad = sA + a_base + mf * (16 * PITCH) + a_coff;
                ldsm4(ah, ad);
                ldsm4(al, ad + MAT_BYTES);
                // product-major: all hh, then all hl, then all lh (RAW dist 4)
#pragma unroll
                for (int nf = 0; nf < 4; nf++)
                    mma_bf16(c[mf][nf], ah, &b[0][nf >> 1][(nf & 1) * 2]);
#pragma unroll
                for (int nf = 0; nf < 4; nf++)
                    mma_bf16(c[mf][nf], ah, &b[1][nf >> 1][(nf & 1) * 2]);
#pragma unroll
                for (int nf = 0; nf < 4; nf++)
                    mma_bf16(c[mf][nf], al, &b[0][nf >> 1][(nf & 1) * 2]);
            }
        }

        if (++slot == 3) slot = 0;
    }

    const int row0 = m0 + wm * 64;
    const int col0 = n0 + wn * 32;
    const int gr = lane >> 2;
    const int gc = (lane & 3) * 2;
#pragma unroll
    for (int mf = 0; mf < 4; mf++)
#pragma unroll
        for (int nf = 0; nf < 4; nf++) {
            float* cc = c[mf][nf];
            const int r = row0 + mf * 16 + gr;
            const int cl = col0 + nf * 8 + gc;
            *(float2*)&Cc[(size_t)r * ldC + cl]       = make_float2(cc[0], cc[1]);
            *(float2*)&Cc[(size_t)(r + 8) * ldC + cl] = make_float2(cc[2], cc[3]);
        }
}

__global__ void __launch_bounds__(256, 2) gemm_qkv_kernel() {
    gemm_bf16x3_body(g_xhi, g_xlo, g_wthi, g_wtlo, g_qkv, DD, DD, DD, QKVW);
}
__global__ void __launch_bounds__(256, 2) gemm_out_kernel(float* __restrict__ out) {
    gemm_bf16x3_body(g_ohi, g_olo, g_wothi, g_wotlo, out, DD, DD, DD, DD);
}

// ---------------------------------------------------------------------------
// RMSNorm + RoPE + bf16 hi/lo split. One warp per 128-vector.
// ---------------------------------------------------------------------------
__global__ void __launch_bounds__(256) norm_rope_split_kernel(
    const int* __restrict__ pos_ids,
    const float* __restrict__ q_norm_w,
    const float* __restrict__ k_norm_w)
{
    const int warp = (blockIdx.x * blockDim.x + threadIdx.x) >> 5;
    const int lane = threadIdx.x & 31;
    const int NQ = TOK * NHEADS;
    const int NK = TOK * KHEADS;

    // --- V path: straight split, no norm/rope ---
    if (warp >= NQ + NK) {
        const int idx = warp - NQ - NK;
        if (idx >= TOK * KHEADS) return;
        const int token = idx >> 3;
        const int kh = idx & 7;
        const float* src = g_qkv + (size_t)token * QKVW + 3072 + kh * HDIM + lane * 4;
        const float4 v = *(const float4*)src;
        __nv_bfloat16 h0 = __float2bfloat16(v.x);
        __nv_bfloat16 h1 = __float2bfloat16(v.y);
        __nv_bfloat16 h2 = __float2bfloat16(v.z);
        __nv_bfloat16 h3 = __float2bfloat16(v.w);
        uint2 hp, lp;
        hp.x = pack_bf2(v.x, v.y);
        hp.y = pack_bf2(v.z, v.w);
        lp.x = pack_bf2(v.x - __bfloat162float(h0), v.y - __bfloat162float(h1));
        lp.y = pack_bf2(v.z - __bfloat162float(h2), v.w - __bfloat162float(h3));
        const size_t off = (size_t)token * 1024 + kh * HDIM + lane * 4;
        *(uint2*)&g_vhi[off] = hp;
        *(uint2*)&g_vlo[off] = lp;
        return;
    }

    const bool isq = warp < NQ;
    int token, hidx;
    const float* vecsrc;
    const float* w;
    if (isq) {
        token = warp >> 4;
        hidx = warp & 15;
        vecsrc = g_qkv + (size_t)token * QKVW + hidx * HDIM;
        w = q_norm_w;
    } else {
        const int kv = warp - NQ;
        token = kv >> 3;
        hidx = kv & 7;
        vecsrc = g_qkv + (size_t)token * QKVW + 2048 + hidx * HDIM;
        w = k_norm_w;
    }
    const int pos = pos_ids[token];

    float4 x4 = *(const float4*)&vecsrc[lane * 4];
    float ss = x4.x * x4.x + x4.y * x4.y + x4.z * x4.z + x4.w * x4.w;
#pragma unroll
    for (int m = 16; m; m >>= 1) ss += __shfl_xor_sync(0xffffffffu, ss, m);
    const float rinv = rsqrtf(ss * (1.0f / HDIM) + EPSV);

    float4 w4 = *(const float4*)&w[lane * 4];
    float n0 = x4.x * w4.x * rinv;
    float n1 = x4.y * w4.y * rinv;
    float n2 = x4.z * w4.z * rinv;
    float n3 = x4.w * w4.w * rinv;

    float p0 = __shfl_xor_sync(0xffffffffu, n0, 16);
    float p1 = __shfl_xor_sync(0xffffffffu, n1, 16);
    float p2 = __shfl_xor_sync(0xffffffffu, n2, 16);
    float p3 = __shfl_xor_sync(0xffffffffu, n3, 16);

    const bool firsthalf = lane < 16;
    const int pbase = (lane & 15) * 4;
    const float fpos = (float)pos;
    const double L2T = 19.931568569324174;   // log2(1e6)
    const float QS = isq ? 0.08838834764831845f * 1.4426950408889634f : 1.0f;

    float nv[4] = {n0, n1, n2, n3};
    float pv[4] = {p0, p1, p2, p3};
    float res[4];
#pragma unroll
    for (int j = 0; j < 4; j++) {
        const int p = pbase + j;
        const float inv_ts = exp2f((float)(-(double)p * L2T / 64.0));
        const float ang = fpos * inv_ts;
        float sv, cv;
        sincosf(ang, &sv, &cv);
        const float r = firsthalf ? (nv[j] * cv - pv[j] * sv)
                                  : (nv[j] * cv + pv[j] * sv);
        res[j] = r * QS;
    }

    __nv_bfloat16 h0 = __float2bfloat16(res[0]);
    __nv_bfloat16 h1 = __float2bfloat16(res[1]);
    __nv_bfloat16 h2 = __float2bfloat16(res[2]);
    __nv_bfloat16 h3 = __float2bfloat16(res[3]);
    uint2 hp, lp;
    hp.x = pack_bf2(res[0], res[1]);
    hp.y = pack_bf2(res[2], res[3]);
    lp.x = pack_bf2(res[0] - __bfloat162float(h0), res[1] - __bfloat162float(h1));
    lp.y = pack_bf2(res[2] - __bfloat162float(h2), res[3] - __bfloat162float(h3));

    if (isq) {
        const size_t off = (size_t)token * 2048 + hidx * HDIM + lane * 4;
        *(uint2*)&g_qhi[off] = hp;
        *(uint2*)&g_qlo[off] = lp;
    } else {
        const size_t off = (size_t)token * 1024 + hidx * HDIM + lane * 4;
        *(uint2*)&g_khi[off] = hp;
        *(uint2*)&g_klo[off] = lp;
    }
}

// ---------------------------------------------------------------------------
// Flash attention on tensor cores (mma.sync bf16, split x3).
//   Block: 128 q-rows x (head n, batch b). 8 warps, warp = 16 q-rows.
//   KV tiles of 64, double-buffered cp.async with SPLIT K/V commit groups.
//   R8: product-major MMA ordering in both QK^T and PV.
// ---------------------------------------------------------------------------
#define FLP 272
#define FL_QSZ (128 * FLP)          // 34816
#define FL_KVSZ (64 * FLP)          // 17408
#define FL_STAGE (4 * FL_KVSZ)      // 69632
#define FL_SMEM (2 * FL_QSZ + 2 * FL_STAGE)   // 208896

__device__ __forceinline__ void fl_prefetch_k(
    uint32_t sbase, int b, int kvh, int kv0, int tid)
{
#pragma unroll
    for (int u = 0; u < 8; u++) {
        const int mtx = u >> 2;                      // 0:Khi 1:Klo
        const int row = ((u & 3) << 4) + (tid >> 4); // 0..63
        const int ch = tid & 15;
        const __nv_bfloat16* g = (mtx ? g_klo : g_khi) +
            (size_t)(b * LL + kv0 + row) * 1024 + kvh * HDIM + ch * 8;
        cp16(sbase + mtx * FL_KVSZ + row * FLP + ch * 16, g);
    }
}
__device__ __forceinline__ void fl_prefetch_v(
    uint32_t sbase, int b, int kvh, int kv0, int tid)
{
#pragma unroll
    for (int u = 0; u < 8; u++) {
        const int mtx = u >> 2;                      // 0:Vhi 1:Vlo
        const int row = ((u & 3) << 4) + (tid >> 4);
        const int ch = tid & 15;
        const __nv_bfloat16* g = (mtx ? g_vlo : g_vhi) +
            (size_t)(b * LL + kv0 + row) * 1024 + kvh * HDIM + ch * 8;
        cp16(sbase + (2 + mtx) * FL_KVSZ + row * FLP + ch * 16, g);
    }
}

__global__ void __launch_bounds__(256, 1) flash_kernel()
{
    const int tid = threadIdx.x;
    const int lane = tid & 31;
    const int wid = tid >> 5;
    const int b = blockIdx.z;
    const int n = blockIdx.y;
    const int mt = (int)gridDim.x - 1 - (int)blockIdx.x;  // big tiles launch first
    const int kvh = n >> 1;
    const int m0 = mt * 128;

    const uint32_t sb = smem_u32(dyn_smem);
    const uint32_t sQhi = sb;
    const uint32_t sQlo = sb + FL_QSZ;
    const uint32_t sStage0 = sb + 2 * FL_QSZ;

    // load Q hi/lo + K0 (group 1), V0 (group 2)
#pragma unroll
    for (int u = 0; u < 16; u++) {
        const int mtx = u >> 3;
        const int row = ((u & 7) << 4) + (tid >> 4);
        const int ch = tid & 15;
        const __nv_bfloat16* g = (mtx ? g_qlo : g_qhi) +
            (size_t)(b * LL + m0 + row) * 2048 + n * HDIM + ch * 8;
        cp16((mtx ? sQlo : sQhi) + row * FLP + ch * 16, g);
    }
    fl_prefetch_k(sStage0, b, kvh, 0, tid);
    CP_COMMIT();
    fl_prefetch_v(sStage0, b, kvh, 0, tid);
    CP_COMMIT();

    float acc[16][4];
#pragma unroll
    for (int i = 0; i < 16; i++)
#pragma unroll
        for (int j = 0; j < 4; j++) acc[i][j] = 0.f;
    float m2[2] = {-1e30f, -1e30f};
    float lsum[2] = {0.f, 0.f};

    const uint32_t a_off = (uint32_t)((wid * 16 + (lane & 15)) * FLP + (lane >> 4) * 16);
    const uint32_t bk_off = (uint32_t)(((lane & 7) + ((lane >> 4) << 3)) * FLP +
                                       ((lane >> 3) & 1) * 16);
    const uint32_t v_off = (uint32_t)(((lane & 7) + ((lane >> 3) & 1) * 8) * FLP +
                                      (lane >> 4) * 16);

    const int nkv = 2 * (mt + 1);
    for (int it = 0; it < nkv; it++) {
        CP_WAIT(1);        // K(it) (+Q on it=0) landed; V(it) may be in flight
        __syncthreads();
        const bool pf = (it + 1 < nkv);
        if (pf) {
            const uint32_t ns = sStage0 + ((it + 1) & 1) * FL_STAGE;
            fl_prefetch_k(ns, b, kvh, (it + 1) * 64, tid);
            CP_COMMIT();
            fl_prefetch_v(ns, b, kvh, (it + 1) * 64, tid);
            CP_COMMIT();
        }
        const uint32_t sKhi = sStage0 + (it & 1) * FL_STAGE;
        const uint32_t sKlo = sKhi + FL_KVSZ;
        const uint32_t sVhi = sKhi + 2 * FL_KVSZ;
        const uint32_t sVlo = sKhi + 3 * FL_KVSZ;

        // --- S = Q K^T (product-major: RAW distance 8) ---
        float sfr[8][4];
#pragma unroll
        for (int i = 0; i < 8; i++)
#pragma unroll
            for (int j = 0; j < 4; j++) sfr[i][j] = 0.f;

#pragma unroll
        for (int kf = 0; kf < 8; kf++) {
            uint32_t ah[4], al[4];
            ldsm4(ah, sQhi + a_off + kf * 32);
            ldsm4(al, sQlo + a_off + kf * 32);
            uint32_t bh[4][4], bl[4][4];
#pragma unroll
            for (int p2 = 0; p2 < 4; p2++) {
                ldsm4(bh[p2], sKhi + bk_off + p2 * 16 * FLP + kf * 32);
                ldsm4(bl[p2], sKlo + bk_off + p2 * 16 * FLP + kf * 32);
            }
#pragma unroll
            for (int p2 = 0; p2 < 4; p2++) {
                mma_bf16(sfr[2 * p2],     ah, bh[p2]);
                mma_bf16(sfr[2 * p2 + 1], ah, bh[p2] + 2);
            }
#pragma unroll
            for (int p2 = 0; p2 < 4; p2++) {
                mma_bf16(sfr[2 * p2],     ah, bl[p2]);
                mma_bf16(sfr[2 * p2 + 1], ah, bl[p2] + 2);
            }
#pragma unroll
            for (int p2 = 0; p2 < 4; p2++) {
                mma_bf16(sfr[2 * p2],     al, bh[p2]);
                mma_bf16(sfr[2 * p2 + 1], al, bh[p2] + 2);
            }
        }

        // --- causal mask (only near-diagonal tiles) ---
        const int rbase = m0 + wid * 16 + (lane >> 2);
        if (it * 64 + 63 > m0 + wid * 16) {
#pragma unroll
            for (int nf = 0; nf < 8; nf++) {
                const int cg = it * 64 + nf * 8 + 2 * (lane & 3);
#pragma unroll
                for (int rg = 0; rg < 4; rg++) {
                    const int row = rbase + (rg >> 1) * 8;
                    const int col = cg + (rg & 1);
                    if (col > row) sfr[nf][rg] = -1e30f;
                }
            }
        }

        // --- online softmax (exp2 domain), warp-local rows ---
#pragma unroll
        for (int h = 0; h < 2; h++) {
            float tm = -1e30f;
#pragma unroll
            for (int nf = 0; nf < 8; nf++)
                tm = fmaxf(tm, fmaxf(sfr[nf][2 * h], sfr[nf][2 * h + 1]));
            tm = fmaxf(tm, __shfl_xor_sync(0xffffffffu, tm, 1));
            tm = fmaxf(tm, __shfl_xor_sync(0xffffffffu, tm, 2));
            const float mn = fmaxf(m2[h], tm);
            const float corr = exp2f(m2[h] - mn);
            m2[h] = mn;
            float rs = 0.f;
#pragma unroll
            for (int nf = 0; nf < 8; nf++) {
                const float e0 = exp2f(sfr[nf][2 * h] - mn);
                const float e1 = exp2f(sfr[nf][2 * h + 1] - mn);
                sfr[nf][2 * h] = e0;
                sfr[nf][2 * h + 1] = e1;
                rs += e0 + e1;
            }
            rs += __shfl_xor_sync(0xffffffffu, rs, 1);
            rs += __shfl_xor_sync(0xffffffffu, rs, 2);
            lsum[h] = lsum[h] * corr + rs;
#pragma unroll
            for (int nf = 0; nf < 16; nf++) {
                acc[nf][2 * h] *= corr;
                acc[nf][2 * h + 1] *= corr;
            }
        }

        // V(it) must be fully landed before PV
        if (pf) { CP_WAIT(2); } else { CP_WAIT(0); }

        // --- O += P V (V-tile pairs, product-major: RAW distance 4) ---
#pragma unroll
        for (int j = 0; j < 4; j++) {
            uint32_t ph[4], pl[4];
#pragma unroll
            for (int q = 0; q < 4; q++) {
                const int nf = 2 * j + (q >> 1);
                const int rb = (q & 1) * 2;
                const float v0 = sfr[nf][rb], v1 = sfr[nf][rb + 1];
                const __nv_bfloat16 h0 = __float2bfloat16(v0);
                const __nv_bfloat16 h1 = __float2bfloat16(v1);
                ph[q] = pack_bf2(v0, v1);
                pl[q] = pack_bf2(v0 - __bfloat162float(h0), v1 - __bfloat162float(h1));
            }
#pragma unroll
            for (int t2 = 0; t2 < 4; t2++) {
                uint32_t vh0[4], vl0[4], vh1[4], vl1[4];
                const uint32_t vb = sVhi + v_off + j * 16 * FLP;
                const uint32_t lb = sVlo + v_off + j * 16 * FLP;
                ldsm4t(vh0, vb + (2 * t2) * 32);
                ldsm4t(vl0, lb + (2 * t2) * 32);
                ldsm4t(vh1, vb + (2 * t2 + 1) * 32);
                ldsm4t(vl1, lb + (2 * t2 + 1) * 32);
                float* a0 = acc[4 * t2];
                float* a1 = acc[4 * t2 + 1];
                float* a2 = acc[4 * t2 + 2];
                float* a3 = acc[4 * t2 + 3];
                mma_bf16(a0, ph, vh0); mma_bf16(a1, ph, vh0 + 2);
                mma_bf16(a2, ph, vh1); mma_bf16(a3, ph, vh1 + 2);
                mma_bf16(a0, ph, vl0); mma_bf16(a1, ph, vl0 + 2);
                mma_bf16(a2, ph, vl1); mma_bf16(a3, ph, vl1 + 2);
                mma_bf16(a0, pl, vh0); mma_bf16(a1, pl, vh0 + 2);
                mma_bf16(a2, pl, vh1); mma_bf16(a3, pl, vh1 + 2);
            }
        }
    }

    // --- finalize: /l, split to bf16 hi/lo, store ---
#pragma unroll
    for (int h = 0; h < 2; h++) {
        const float inv = 1.0f / lsum[h];
        const int row = m0 + wid * 16 + (lane >> 2) + h * 8;
        const size_t base = (size_t)(b * LL + row) * 2048 + n * HDIM + 2 * (lane & 3);
#pragma unroll
        for (int nf = 0; nf < 16; nf++) {
            const float v0 = acc[nf][2 * h] * inv;
            const float v1 = acc[nf][2 * h + 1] * inv;
            const __nv_bfloat16 h0 = __float2bfloat16(v0);
            const __nv_bfloat16 h1 = __float2bfloat16(v1);
            *(uint32_t*)&g_ohi[base + nf * 8] = pack_bf2(v0, v1);
            *(uint32_t*)&g_olo[base + nf * 8] =
                pack_bf2(v0 - __bfloat162float(h0), v1 - __bfloat162float(h1));
        }
    }
}

// ---------------------------------------------------------------------------
// Launch
// ---------------------------------------------------------------------------
extern "C" void kernel_launch(void* const* d_in, const int* in_sizes, int n_in,
                              void* d_out, int out_size)
{
    const float* x   = (const float*)d_in[0];
    const int*   pos = (const int*)d_in[1];
    // d_in[2] = attn_mask (causal tril) — implied analytically, unused
    const float* wq  = (const float*)d_in[3];
    const float* wk  = (const float*)d_in[4];
    const float* wv  = (const float*)d_in[5];
    const float* wo  = (const float*)d_in[6];
    const float* qnw = (const float*)d_in[7];
    const float* knw = (const float*)d_in[8];
    float* out = (float*)d_out;

    cudaFuncSetAttribute(gemm_qkv_kernel,
                         cudaFuncAttributeMaxDynamicSharedMemorySize, GEMM_SMEM_BYTES);
    cudaFuncSetAttribute(gemm_out_kernel,
                         cudaFuncAttributeMaxDynamicSharedMemorySize, GEMM_SMEM_BYTES);
    cudaFuncSetAttribute(flash_kernel,
                         cudaFuncAttributeMaxDynamicSharedMemorySize, FL_SMEM);

    // 1. weights -> transposed bf16 hi/lo (one launch for all four)
    transpose_convert_all_kernel<<<dim3(64, 64, 4), dim3(32, 8)>>>(wq, wk, wv, wo);

    // 2. split X
    convert_split_x_kernel<<<(TOK * DD / 4 + 255) / 256, 256>>>(x);

    // 3. QKV projection
    gemm_qkv_kernel<<<dim3(QKVW / 128, TOK / 128), 256, GEMM_SMEM_BYTES>>>();

    // 4. RMSNorm + RoPE + split (q,k,v)
    {
        const int nwarps = TOK * (NHEADS + 2 * KHEADS);   // 131072
        const int blocks = nwarps * 32 / 256;
        norm_rope_split_kernel<<<blocks, 256>>>(pos, qnw, knw);
    }

    // 5. Flash attention (tensor cores)
    flash_kernel<<<dim3(LL / 128, NHEADS, BB), 256, FL_SMEM>>>();

    // 6. output projection
    gemm_out_kernel<<<dim3(DD / 128, TOK / 128), 256, GEMM_SMEM_BYTES>>>(out);
}

// round 9
// speedup vs baseline: 1.2928x; 1.0809x over previous
#include <cuda_runtime.h>
#include <cuda_bf16.h>
#include <math.h>
#include <stdint.h>

// Problem constants
#define BB 2
#define LL 2048
#define DD 2048
#define NHEADS 16
#define KHEADS 8
#define HDIM 128
#define TOK (BB * LL)        // 4096
#define EPSV 1e-6f
#define QKVW 4096            // concatenated qkv col space (q:0..2047, k:..3071, v:..4095)

// ---------------------------------------------------------------------------
// Scratch (device globals — no runtime allocation allowed)
// ---------------------------------------------------------------------------
__device__ __align__(16) __nv_bfloat16 g_xhi[(size_t)TOK * DD];
__device__ __align__(16) __nv_bfloat16 g_xlo[(size_t)TOK * DD];
__device__ __align__(16) __nv_bfloat16 g_qhi[(size_t)TOK * DD];     // normed/rope'd/pre-scaled q
__device__ __align__(16) __nv_bfloat16 g_qlo[(size_t)TOK * DD];
__device__ __align__(16) __nv_bfloat16 g_khi[(size_t)TOK * KHEADS * HDIM];
__device__ __align__(16) __nv_bfloat16 g_klo[(size_t)TOK * KHEADS * HDIM];
__device__ __align__(16) __nv_bfloat16 g_vhi[(size_t)TOK * KHEADS * HDIM];
__device__ __align__(16) __nv_bfloat16 g_vlo[(size_t)TOK * KHEADS * HDIM];
__device__ __align__(16) __nv_bfloat16 g_ohi[(size_t)TOK * DD];     // attention out
__device__ __align__(16) __nv_bfloat16 g_olo[(size_t)TOK * DD];
__device__ __align__(16) __nv_bfloat16 g_wthi[(size_t)QKVW * DD];   // [n][k] qkv weights
__device__ __align__(16) __nv_bfloat16 g_wtlo[(size_t)QKVW * DD];
__device__ __align__(16) __nv_bfloat16 g_wothi[(size_t)DD * DD];    // [n][k] wo
__device__ __align__(16) __nv_bfloat16 g_wotlo[(size_t)DD * DD];
__device__ __align__(16) float g_rsin[(size_t)TOK * 64];            // rope tables
__device__ __align__(16) float g_rcos[(size_t)TOK * 64];

extern __shared__ char dyn_smem[];

// ---------------------------------------------------------------------------
// PTX helpers (family-portable: cp.async / ldmatrix / mma.sync)
// ---------------------------------------------------------------------------
__device__ __forceinline__ uint32_t smem_u32(const void* p) {
    uint32_t a;
    asm("{ .reg .u64 t; cvta.to.shared.u64 t, %1; cvt.u32.u64 %0, t; }"
        : "=r"(a) : "l"(p));
    return a;
}

__device__ __forceinline__ void cp16(uint32_t dst, const void* src) {
    asm volatile("cp.async.cg.shared.global [%0], [%1], 16;" :: "r"(dst), "l"(src));
}
#define CP_COMMIT() asm volatile("cp.async.commit_group;" ::: "memory")
#define CP_WAIT(N)  asm volatile("cp.async.wait_group %0;" :: "n"(N) : "memory")

__device__ __forceinline__ void ldsm4(uint32_t* r, uint32_t a) {
    asm volatile("ldmatrix.sync.aligned.m8n8.x4.shared.b16 {%0,%1,%2,%3}, [%4];"
        : "=r"(r[0]), "=r"(r[1]), "=r"(r[2]), "=r"(r[3]) : "r"(a));
}
__device__ __forceinline__ void ldsm4t(uint32_t* r, uint32_t a) {
    asm volatile("ldmatrix.sync.aligned.m8n8.x4.trans.shared.b16 {%0,%1,%2,%3}, [%4];"
        : "=r"(r[0]), "=r"(r[1]), "=r"(r[2]), "=r"(r[3]) : "r"(a));
}

__device__ __forceinline__ void mma_bf16(float* c, const uint32_t* a, const uint32_t* b) {
    asm volatile(
        "mma.sync.aligned.m16n8k16.row.col.f32.bf16.bf16.f32 "
        "{%0,%1,%2,%3}, {%4,%5,%6,%7}, {%8,%9}, {%0,%1,%2,%3};"
        : "+f"(c[0]), "+f"(c[1]), "+f"(c[2]), "+f"(c[3])
        : "r"(a[0]), "r"(a[1]), "r"(a[2]), "r"(a[3]), "r"(b[0]), "r"(b[1]));
}

__device__ __forceinline__ uint32_t pack_bf2(float x, float y) {
    __nv_bfloat162 t;
    t.x = __float2bfloat16(x);
    t.y = __float2bfloat16(y);
    return *(uint32_t*)&t;
}

// ---------------------------------------------------------------------------
// Conversion / table kernels
// ---------------------------------------------------------------------------
__global__ void __launch_bounds__(256) transpose_convert_all_kernel(
    const float* __restrict__ wq, const float* __restrict__ wk,
    const float* __restrict__ wv, const float* __restrict__ wo)
{
    const int z = blockIdx.z;
    const float* src;
    int C, row_off;
    __nv_bfloat16 *dhi, *dlo;
    if (z == 0)      { src = wq; C = 2048; row_off = 0;    dhi = g_wthi;  dlo = g_wtlo;  }
    else if (z == 1) { if (blockIdx.x >= 32) return;
                       src = wk; C = 1024; row_off = 2048; dhi = g_wthi;  dlo = g_wtlo;  }
    else if (z == 2) { if (blockIdx.x >= 32) return;
                       src = wv; C = 1024; row_off = 3072; dhi = g_wthi;  dlo = g_wtlo;  }
    else             { src = wo; C = 2048; row_off = 0;    dhi = g_wothi; dlo = g_wotlo; }

    __shared__ float t[32][33];
    const int c0 = blockIdx.x * 32;
    const int r0 = blockIdx.y * 32;
    const int tx = threadIdx.x;
    const int ty = threadIdx.y;

#pragma unroll
    for (int j = 0; j < 4; j++)
        t[ty + j * 8][tx] = src[(size_t)(r0 + ty + j * 8) * C + c0 + tx];
    __syncthreads();

#pragma unroll
    for (int j = 0; j < 4; j++) {
        const int i = ty + j * 8;
        const float v = t[tx][i];
        const __nv_bfloat16 h = __float2bfloat16(v);
        const __nv_bfloat16 l = __float2bfloat16(v - __bfloat162float(h));
        const size_t off = (size_t)(row_off + c0 + i) * DD + r0 + tx;
        dhi[off] = h;
        dlo[off] = l;
    }
}

__global__ void __launch_bounds__(256) convert_split_x_kernel(const float* __restrict__ src)
{
    const size_t i = (size_t)blockIdx.x * blockDim.x + threadIdx.x;
    const size_t n4 = (size_t)TOK * DD / 4;
    if (i >= n4) return;
    const float4 v = ((const float4*)src)[i];
    __nv_bfloat16 h0 = __float2bfloat16(v.x);
    __nv_bfloat16 h1 = __float2bfloat16(v.y);
    __nv_bfloat16 h2 = __float2bfloat16(v.z);
    __nv_bfloat16 h3 = __float2bfloat16(v.w);
    uint2 hp, lp;
    hp.x = pack_bf2(v.x, v.y);
    hp.y = pack_bf2(v.z, v.w);
    lp.x = pack_bf2(v.x - __bfloat162float(h0), v.y - __bfloat162float(h1));
    lp.y = pack_bf2(v.z - __bfloat162float(h2), v.w - __bfloat162float(h3));
    ((uint2*)g_xhi)[i] = hp;
    ((uint2*)g_xlo)[i] = lp;
}

// RoPE tables: sin/cos per (token, freq-pair). One-time, full-precision.
__global__ void __launch_bounds__(256) rope_table_kernel(const int* __restrict__ pos_ids)
{
    const int idx = blockIdx.x * 256 + threadIdx.x;
    if (idx >= TOK * 64) return;
    const int token = idx >> 6;
    const int p = idx & 63;
    const double L2T = 19.931568569324174;   // log2(1e6)
    const float inv_ts = exp2f((float)(-(double)p * L2T / 64.0));
    const float ang = (float)pos_ids[token] * inv_ts;
    float sv, cv;
    sincosf(ang, &sv, &cv);
    g_rsin[idx] = sv;
    g_rcos[idx] = cv;
}

// ---------------------------------------------------------------------------
// split-bf16 warp-MMA GEMM: C[M x N] = A[M x K] * B[N x K]^T
//   CTA tile 128x128, BK=32, 256 threads, 8 warps (2m x 4n), warp tile 64x32.
//   XOR-swizzled 64B pitch, 3-stage cp.async ring, 2 CTAs/SM, product-major MMAs.
//   FUSED=1 (qkv): epilogue does RMSNorm+RoPE+split in-SMEM, writes q/k/v splits.
//   FUSED=0 (out): plain fp32 global stores.
// ---------------------------------------------------------------------------
#define BK 32
#define PITCH 64
#define MAT_BYTES (128 * PITCH)           // 8192 per split
#define STAGE_BYTES (4 * MAT_BYTES)       // 32768
#define GEMM_SMEM_BYTES (3 * STAGE_BYTES) // 98304 (x2 CTAs = 196KB)
#define EPI_PITCH 132                     // fp32 words per row in epilogue buffer

__device__ __forceinline__ uint32_t gswz(int r, int c) {
    return (uint32_t)(r * PITCH + ((c ^ ((r >> 1) & 3)) << 4));
}

__device__ __forceinline__ void prefetch_stage(
    uint32_t sbase,
    const __nv_bfloat16* __restrict__ Ahi, const __nv_bfloat16* __restrict__ Alo,
    const __nv_bfloat16* __restrict__ Bhi, const __nv_bfloat16* __restrict__ Blo,
    int m0, int n0, int k0, int ldA, int ldB, int tid)
{
#pragma unroll
    for (int j = 0; j < 2; j++) {
        const int id = tid * 2 + j;
        const int r = id >> 2;
        const int c = id & 3;
        const uint32_t soff = gswz(r, c);
        const size_t ga = (size_t)(m0 + r) * ldA + k0 + c * 8;
        const size_t gb = (size_t)(n0 + r) * ldB + k0 + c * 8;
        cp16(sbase + soff,                 Ahi + ga);
        cp16(sbase + MAT_BYTES + soff,     Alo + ga);
        cp16(sbase + 2 * MAT_BYTES + soff, Bhi + gb);
        cp16(sbase + 3 * MAT_BYTES + soff, Blo + gb);
    }
}

template <int FUSED>
__device__ __forceinline__ void gemm_bf16x3_body(
    const __nv_bfloat16* __restrict__ Ahi, const __nv_bfloat16* __restrict__ Alo,
    const __nv_bfloat16* __restrict__ Bhi, const __nv_bfloat16* __restrict__ Blo,
    float* __restrict__ Cc, int K, int ldA, int ldB, int ldC,
    const float* __restrict__ qnw, const float* __restrict__ knw)
{
    const int tid  = threadIdx.x;             // 256 threads
    const int lane = tid & 31;
    const int wid  = tid >> 5;                // 0..7
    const int wm   = wid & 1;
    const int wn   = wid >> 1;
    const int m0   = blockIdx.y * 128;
    const int n0   = blockIdx.x * 128;
    const uint32_t smem_base = smem_u32(dyn_smem);

    float c[4][4][4];
#pragma unroll
    for (int i = 0; i < 4; i++)
#pragma unroll
        for (int j = 0; j < 4; j++)
#pragma unroll
            for (int k = 0; k < 4; k++) c[i][j][k] = 0.f;

    const int a_row  = wm * 64 + (lane & 15);
    const int a_swz  = (a_row >> 1) & 3;
    const uint32_t a_base = (uint32_t)(a_row * PITCH);
    const int a_c0   = lane >> 4;
    const int b_row  = wn * 32 + (lane & 7) + ((lane >> 4) << 3);
    const int b_swz  = (b_row >> 1) & 3;
    const uint32_t b_base = (uint32_t)(b_row * PITCH);
    const int b_c0   = (lane >> 3) & 1;

    const int nk = K / BK;

    prefetch_stage(smem_base, Ahi, Alo, Bhi, Blo, m0, n0, 0, ldA, ldB, tid);
    CP_COMMIT();
    prefetch_stage(smem_base + STAGE_BYTES, Ahi, Alo, Bhi, Blo, m0, n0, BK, ldA, ldB, tid);
    CP_COMMIT();

    int slot = 0;
    for (int it = 0; it < nk; it++) {
        if (it < nk - 1) { CP_WAIT(1); } else { CP_WAIT(0); }
        __syncthreads();

        if (it + 2 < nk) {
            int ps = slot + 2;
            if (ps >= 3) ps -= 3;
            prefetch_stage(smem_base + ps * STAGE_BYTES,
                           Ahi, Alo, Bhi, Blo, m0, n0, (it + 2) * BK, ldA, ldB, tid);
            CP_COMMIT();
        }

        const uint32_t sA = smem_base + slot * STAGE_BYTES;
        const uint32_t sB = sA + 2 * MAT_BYTES;

#pragma unroll
        for (int kf = 0; kf < 2; kf++) {
            uint32_t b[2][2][4];
            const uint32_t a_coff = (uint32_t)(((a_c0 + kf * 2) ^ a_swz) << 4);
            const uint32_t b_coff = (uint32_t)(((b_c0 + kf * 2) ^ b_swz) << 4);
#pragma unroll
            for (int nf2 = 0; nf2 < 2; nf2++) {
                const uint32_t bd = sB + b_base + nf2 * (16 * PITCH) + b_coff;
                ldsm4(b[0][nf2], bd);
                ldsm4(b[1][nf2], bd + MAT_BYTES);
            }
#pragma unroll
            for (int mf = 0; mf < 4; mf++) {
                uint32_t ah[4], al[4];
                const uint32_t ad = sA + a_base + mf * (16 * PITCH) + a_coff;
                ldsm4(ah, ad);
                ldsm4(al, ad + MAT_BYTES);
#pragma unroll
                for (int nf = 0; nf < 4; nf++)
                    mma_bf16(c[mf][nf], ah, &b[0][nf >> 1][(nf & 1) * 2]);
#pragma unroll
                for (int nf = 0; nf < 4; nf++)
                    mma_bf16(c[mf][nf], ah, &b[1][nf >> 1][(nf & 1) * 2]);
#pragma unroll
                for (int nf = 0; nf < 4; nf++)
                    mma_bf16(c[mf][nf], al, &b[0][nf >> 1][(nf & 1) * 2]);
            }
        }

        if (++slot == 3) slot = 0;
    }

    const int gr = lane >> 2;
    const int gc = (lane & 3) * 2;

    if (FUSED == 0) {
        // plain epilogue: direct fp32 stores
        const int row0 = m0 + wm * 64;
        const int col0 = n0 + wn * 32;
#pragma unroll
        for (int mf = 0; mf < 4; mf++)
#pragma unroll
            for (int nf = 0; nf < 4; nf++) {
                float* cc = c[mf][nf];
                const int r = row0 + mf * 16 + gr;
                const int cl = col0 + nf * 8 + gc;
                *(float2*)&Cc[(size_t)r * ldC + cl]       = make_float2(cc[0], cc[1]);
                *(float2*)&Cc[(size_t)(r + 8) * ldC + cl] = make_float2(cc[2], cc[3]);
            }
        return;
    }

    // --- FUSED epilogue: SMEM bounce + RMSNorm + RoPE + hi/lo split ---
    float* Sb = (float*)dyn_smem;   // [128][EPI_PITCH] fp32, aliases stage ring
    __syncthreads();                // all warps done with stage SMEM
    {
        const int row0 = wm * 64;
        const int col0 = wn * 32;
#pragma unroll
        for (int mf = 0; mf < 4; mf++)
#pragma unroll
            for (int nf = 0; nf < 4; nf++) {
                float* cc = c[mf][nf];
                const int r = row0 + mf * 16 + gr;
                const int cl = col0 + nf * 8 + gc;
                *(float2*)&Sb[r * EPI_PITCH + cl]       = make_float2(cc[0], cc[1]);
                *(float2*)&Sb[(r + 8) * EPI_PITCH + cl] = make_float2(cc[2], cc[3]);
            }
    }
    __syncthreads();

    const bool isq = (n0 < 2048);
    const bool isv = (n0 >= 3072);
    __nv_bfloat16 *dhi, *dlo;
    int colbase, ldd;
    if (isq)              { dhi = g_qhi; dlo = g_qlo; colbase = n0;        ldd = 2048; }
    else if (n0 < 3072)   { dhi = g_khi; dlo = g_klo; colbase = n0 - 2048; ldd = 1024; }
    else                  { dhi = g_vhi; dlo = g_vlo; colbase = n0 - 3072; ldd = 1024; }

    // scale * log2(e) folded into q for exp2-domain softmax
    const float QS = isq ? 0.08838834764831845f * 1.4426950408889634f : 1.0f;
    const bool firsthalf = lane < 16;
    const int pbase = (lane & 15) * 4;

    float4 w4 = make_float4(1.f, 1.f, 1.f, 1.f);
    if (!isv) {
        const float* nw = isq ? qnw : knw;
        w4 = *(const float4*)&nw[lane * 4];
    }

#pragma unroll 1
    for (int i = 0; i < 16; i++) {
        const int row = wid * 16 + i;
        const int token = m0 + row;
        float4 xv = *(float4*)&Sb[row * EPI_PITCH + lane * 4];
        float r0, r1, r2, r3;
        if (!isv) {
            float ss = xv.x * xv.x + xv.y * xv.y + xv.z * xv.z + xv.w * xv.w;
#pragma unroll
            for (int m = 16; m; m >>= 1) ss += __shfl_xor_sync(0xffffffffu, ss, m);
            const float rinv = rsqrtf(ss * (1.0f / HDIM) + EPSV);
            const float nn0 = xv.x * w4.x * rinv;
            const float nn1 = xv.y * w4.y * rinv;
            const float nn2 = xv.z * w4.z * rinv;
            const float nn3 = xv.w * w4.w * rinv;
            const float pp0 = __shfl_xor_sync(0xffffffffu, nn0, 16);
            const float pp1 = __shfl_xor_sync(0xffffffffu, nn1, 16);
            const float pp2 = __shfl_xor_sync(0xffffffffu, nn2, 16);
            const float pp3 = __shfl_xor_sync(0xffffffffu, nn3, 16);
            const float4 sn = *(const float4*)&g_rsin[(size_t)token * 64 + pbase];
            const float4 cs = *(const float4*)&g_rcos[(size_t)token * 64 + pbase];
            if (firsthalf) {
                r0 = (nn0 * cs.x - pp0 * sn.x) * QS;
                r1 = (nn1 * cs.y - pp1 * sn.y) * QS;
                r2 = (nn2 * cs.z - pp2 * sn.z) * QS;
                r3 = (nn3 * cs.w - pp3 * sn.w) * QS;
            } else {
                r0 = (nn0 * cs.x + pp0 * sn.x) * QS;
                r1 = (nn1 * cs.y + pp1 * sn.y) * QS;
                r2 = (nn2 * cs.z + pp2 * sn.z) * QS;
                r3 = (nn3 * cs.w + pp3 * sn.w) * QS;
            }
        } else {
            r0 = xv.x; r1 = xv.y; r2 = xv.z; r3 = xv.w;
        }
        const __nv_bfloat16 h0 = __float2bfloat16(r0);
        const __nv_bfloat16 h1 = __float2bfloat16(r1);
        const __nv_bfloat16 h2 = __float2bfloat16(r2);
        const __nv_bfloat16 h3 = __float2bfloat16(r3);
        uint2 hp, lp;
        hp.x = pack_bf2(r0, r1);
        hp.y = pack_bf2(r2, r3);
        lp.x = pack_bf2(r0 - __bfloat162float(h0), r1 - __bfloat162float(h1));
        lp.y = pack_bf2(r2 - __bfloat162float(h2), r3 - __bfloat162float(h3));
        const size_t off = (size_t)token * ldd + colbase + lane * 4;
        *(uint2*)&dhi[off] = hp;
        *(uint2*)&dlo[off] = lp;
    }
}

__global__ void __launch_bounds__(256, 2) gemm_qkv_kernel(
    const float* __restrict__ qnw, const float* __restrict__ knw) {
    gemm_bf16x3_body<1>(g_xhi, g_xlo, g_wthi, g_wtlo, nullptr, DD, DD, DD, 0, qnw, knw);
}
__global__ void __launch_bounds__(256, 2) gemm_out_kernel(float* __restrict__ out) {
    gemm_bf16x3_body<0>(g_ohi, g_olo, g_wothi, g_wotlo, out, DD, DD, DD, DD,
                        nullptr, nullptr);
}

// ---------------------------------------------------------------------------
// Flash attention on tensor cores (mma.sync bf16, split x3).
//   Block: 128 q-rows x (head n, batch b). 8 warps, warp = 16 q-rows.
//   KV tiles of 64, double-buffered cp.async with SPLIT K/V commit groups.
//   Product-major MMA ordering in both QK^T and PV.
// ---------------------------------------------------------------------------
#define FLP 272
#define FL_QSZ (128 * FLP)          // 34816
#define FL_KVSZ (64 * FLP)          // 17408
#define FL_STAGE (4 * FL_KVSZ)      // 69632
#define FL_SMEM (2 * FL_QSZ + 2 * FL_STAGE)   // 208896

__device__ __forceinline__ void fl_prefetch_k(
    uint32_t sbase, int b, int kvh, int kv0, int tid)
{
#pragma unroll
    for (int u = 0; u < 8; u++) {
        const int mtx = u >> 2;                      // 0:Khi 1:Klo
        const int row = ((u & 3) << 4) + (tid >> 4); // 0..63
        const int ch = tid & 15;
        const __nv_bfloat16* g = (mtx ? g_klo : g_khi) +
            (size_t)(b * LL + kv0 + row) * 1024 + kvh * HDIM + ch * 8;
        cp16(sbase + mtx * FL_KVSZ + row * FLP + ch * 16, g);
    }
}
__device__ __forceinline__ void fl_prefetch_v(
    uint32_t sbase, int b, int kvh, int kv0, int tid)
{
#pragma unroll
    for (int u = 0; u < 8; u++) {
        const int mtx = u >> 2;                      // 0:Vhi 1:Vlo
        const int row = ((u & 3) << 4) + (tid >> 4);
        const int ch = tid & 15;
        const __nv_bfloat16* g = (mtx ? g_vlo : g_vhi) +
            (size_t)(b * LL + kv0 + row) * 1024 + kvh * HDIM + ch * 8;
        cp16(sbase + (2 + mtx) * FL_KVSZ + row * FLP + ch * 16, g);
    }
}

__global__ void __launch_bounds__(256, 1) flash_kernel()
{
    const int tid = threadIdx.x;
    const int lane = tid & 31;
    const int wid = tid >> 5;
    const int b = blockIdx.z;
    const int n = blockIdx.y;
    const int mt = (int)gridDim.x - 1 - (int)blockIdx.x;  // big tiles launch first
    const int kvh = n >> 1;
    const int m0 = mt * 128;

    const uint32_t sb = smem_u32(dyn_smem);
    const uint32_t sQhi = sb;
    const uint32_t sQlo = sb + FL_QSZ;
    const uint32_t sStage0 = sb + 2 * FL_QSZ;

    // load Q hi/lo + K0 (group 1), V0 (group 2)
#pragma unroll
    for (int u = 0; u < 16; u++) {
        const int mtx = u >> 3;
        const int row = ((u & 7) << 4) + (tid >> 4);
        const int ch = tid & 15;
        const __nv_bfloat16* g = (mtx ? g_qlo : g_qhi) +
            (size_t)(b * LL + m0 + row) * 2048 + n * HDIM + ch * 8;
        cp16((mtx ? sQlo : sQhi) + row * FLP + ch * 16, g);
    }
    fl_prefetch_k(sStage0, b, kvh, 0, tid);
    CP_COMMIT();
    fl_prefetch_v(sStage0, b, kvh, 0, tid);
    CP_COMMIT();

    float acc[16][4];
#pragma unroll
    for (int i = 0; i < 16; i++)
#pragma unroll
        for (int j = 0; j < 4; j++) acc[i][j] = 0.f;
    float m2[2] = {-1e30f, -1e30f};
    float lsum[2] = {0.f, 0.f};

    const uint32_t a_off = (uint32_t)((wid * 16 + (lane & 15)) * FLP + (lane >> 4) * 16);
    const uint32_t bk_off = (uint32_t)(((lane & 7) + ((lane >> 4) << 3)) * FLP +
                                       ((lane >> 3) & 1) * 16);
    const uint32_t v_off = (uint32_t)(((lane & 7) + ((lane >> 3) & 1) * 8) * FLP +
                                      (lane >> 4) * 16);

    const int nkv = 2 * (mt + 1);
    for (int it = 0; it < nkv; it++) {
        CP_WAIT(1);        // K(it) (+Q on it=0) landed; V(it) may be in flight
        __syncthreads();
        const bool pf = (it + 1 < nkv);
        if (pf) {
            const uint32_t ns = sStage0 + ((it + 1) & 1) * FL_STAGE;
            fl_prefetch_k(ns, b, kvh, (it + 1) * 64, tid);
            CP_COMMIT();
            fl_prefetch_v(ns, b, kvh, (it + 1) * 64, tid);
            CP_COMMIT();
        }
        const uint32_t sKhi = sStage0 + (it & 1) * FL_STAGE;
        const uint32_t sKlo = sKhi + FL_KVSZ;
        const uint32_t sVhi = sKhi + 2 * FL_KVSZ;
        const uint32_t sVlo = sKhi + 3 * FL_KVSZ;

        // --- S = Q K^T (product-major) ---
        float sfr[8][4];
#pragma unroll
        for (int i = 0; i < 8; i++)
#pragma unroll
            for (int j = 0; j < 4; j++) sfr[i][j] = 0.f;

#pragma unroll
        for (int kf = 0; kf < 8; kf++) {
            uint32_t ah[4], al[4];
            ldsm4(ah, sQhi + a_off + kf * 32);
            ldsm4(al, sQlo + a_off + kf * 32);
            uint32_t bh[4][4], bl[4][4];
#pragma unroll
            for (int p2 = 0; p2 < 4; p2++) {
                ldsm4(bh[p2], sKhi + bk_off + p2 * 16 * FLP + kf * 32);
                ldsm4(bl[p2], sKlo + bk_off + p2 * 16 * FLP + kf * 32);
            }
#pragma unroll
            for (int p2 = 0; p2 < 4; p2++) {
                mma_bf16(sfr[2 * p2],     ah, bh[p2]);
                mma_bf16(sfr[2 * p2 + 1], ah, bh[p2] + 2);
            }
#pragma unroll
            for (int p2 = 0; p2 < 4; p2++) {
                mma_bf16(sfr[2 * p2],     ah, bl[p2]);
                mma_bf16(sfr[2 * p2 + 1], ah, bl[p2] + 2);
            }
#pragma unroll
            for (int p2 = 0; p2 < 4; p2++) {
                mma_bf16(sfr[2 * p2],     al, bh[p2]);
                mma_bf16(sfr[2 * p2 + 1], al, bh[p2] + 2);
            }
        }

        // --- causal mask (only near-diagonal tiles) ---
        const int rbase = m0 + wid * 16 + (lane >> 2);
        if (it * 64 + 63 > m0 + wid * 16) {
#pragma unroll
            for (int nf = 0; nf < 8; nf++) {
                const int cg = it * 64 + nf * 8 + 2 * (lane & 3);
#pragma unroll
                for (int rg = 0; rg < 4; rg++) {
                    const int row = rbase + (rg >> 1) * 8;
                    const int col = cg + (rg & 1);
                    if (col > row) sfr[nf][rg] = -1e30f;
                }
            }
        }

        // --- online softmax (exp2 domain), warp-local rows ---
#pragma unroll
        for (int h = 0; h < 2; h++) {
            float tm = -1e30f;
#pragma unroll
            for (int nf = 0; nf < 8; nf++)
                tm = fmaxf(tm, fmaxf(sfr[nf][2 * h], sfr[nf][2 * h + 1]));
            tm = fmaxf(tm, __shfl_xor_sync(0xffffffffu, tm, 1));
            tm = fmaxf(tm, __shfl_xor_sync(0xffffffffu, tm, 2));
            const float mn = fmaxf(m2[h], tm);
            const float corr = exp2f(m2[h] - mn);
            m2[h] = mn;
            float rs = 0.f;
#pragma unroll
            for (int nf = 0; nf < 8; nf++) {
                const float e0 = exp2f(sfr[nf][2 * h] - mn);
                const float e1 = exp2f(sfr[nf][2 * h + 1] - mn);
                sfr[nf][2 * h] = e0;
                sfr[nf][2 * h + 1] = e1;
                rs += e0 + e1;
            }
            rs += __shfl_xor_sync(0xffffffffu, rs, 1);
            rs += __shfl_xor_sync(0xffffffffu, rs, 2);
            lsum[h] = lsum[h] * corr + rs;
#pragma unroll
            for (int nf = 0; nf < 16; nf++) {
                acc[nf][2 * h] *= corr;
                acc[nf][2 * h + 1] *= corr;
            }
        }

        // V(it) must be fully landed before PV
        if (pf) { CP_WAIT(2); } else { CP_WAIT(0); }

        // --- O += P V (V-tile pairs, product-major) ---
#pragma unroll
        for (int j = 0; j < 4; j++) {
            uint32_t ph[4], pl[4];
#pragma unroll
            for (int q = 0; q < 4; q++) {
                const int nf = 2 * j + (q >> 1);
                const int rb = (q & 1) * 2;
                const float v0 = sfr[nf][rb], v1 = sfr[nf][rb + 1];
                const __nv_bfloat16 h0 = __float2bfloat16(v0);
                const __nv_bfloat16 h1 = __float2bfloat16(v1);
                ph[q] = pack_bf2(v0, v1);
                pl[q] = pack_bf2(v0 - __bfloat162float(h0), v1 - __bfloat162float(h1));
            }
#pragma unroll
            for (int t2 = 0; t2 < 4; t2++) {
                uint32_t vh0[4], vl0[4], vh1[4], vl1[4];
                const uint32_t vb = sVhi + v_off + j * 16 * FLP;
                const uint32_t lb = sVlo + v_off + j * 16 * FLP;
                ldsm4t(vh0, vb + (2 * t2) * 32);
                ldsm4t(vl0, lb + (2 * t2) * 32);
                ldsm4t(vh1, vb + (2 * t2 + 1) * 32);
                ldsm4t(vl1, lb + (2 * t2 + 1) * 32);
                float* a0 = acc[4 * t2];
                float* a1 = acc[4 * t2 + 1];
                float* a2 = acc[4 * t2 + 2];
                float* a3 = acc[4 * t2 + 3];
                mma_bf16(a0, ph, vh0); mma_bf16(a1, ph, vh0 + 2);
                mma_bf16(a2, ph, vh1); mma_bf16(a3, ph, vh1 + 2);
                mma_bf16(a0, ph, vl0); mma_bf16(a1, ph, vl0 + 2);
                mma_bf16(a2, ph, vl1); mma_bf16(a3, ph, vl1 + 2);
                mma_bf16(a0, pl, vh0); mma_bf16(a1, pl, vh0 + 2);
                mma_bf16(a2, pl, vh1); mma_bf16(a3, pl, vh1 + 2);
            }
        }
    }

    // --- finalize: /l, split to bf16 hi/lo, store ---
#pragma unroll
    for (int h = 0; h < 2; h++) {
        const float inv = 1.0f / lsum[h];
        const int row = m0 + wid * 16 + (lane >> 2) + h * 8;
        const size_t base = (size_t)(b * LL + row) * 2048 + n * HDIM + 2 * (lane & 3);
#pragma unroll
        for (int nf = 0; nf < 16; nf++) {
            const float v0 = acc[nf][2 * h] * inv;
            const float v1 = acc[nf][2 * h + 1] * inv;
            const __nv_bfloat16 h0 = __float2bfloat16(v0);
            const __nv_bfloat16 h1 = __float2bfloat16(v1);
            *(uint32_t*)&g_ohi[base + nf * 8] = pack_bf2(v0, v1);
            *(uint32_t*)&g_olo[base + nf * 8] =
                pack_bf2(v0 - __bfloat162float(h0), v1 - __bfloat162float(h1));
        }
    }
}

// ---------------------------------------------------------------------------
// Launch
// ---------------------------------------------------------------------------
extern "C" void kernel_launch(void* const* d_in, const int* in_sizes, int n_in,
                              void* d_out, int out_size)
{
    const float* x   = (const float*)d_in[0];
    const int*   pos = (const int*)d_in[1];
    // d_in[2] = attn_mask (causal tril) — implied analytically, unused
    const float* wq  = (const float*)d_in[3];
    const float* wk  = (const float*)d_in[4];
    const float* wv  = (const float*)d_in[5];
    const float* wo  = (const float*)d_in[6];
    const float* qnw = (const float*)d_in[7];
    const float* knw = (const float*)d_in[8];
    float* out = (float*)d_out;

    cudaFuncSetAttribute(gemm_qkv_kernel,
                         cudaFuncAttributeMaxDynamicSharedMemorySize, GEMM_SMEM_BYTES);
    cudaFuncSetAttribute(gemm_out_kernel,
                         cudaFuncAttributeMaxDynamicSharedMemorySize, GEMM_SMEM_BYTES);
    cudaFuncSetAttribute(flash_kernel,
                         cudaFuncAttributeMaxDynamicSharedMemorySize, FL_SMEM);

    // 1. weights -> transposed bf16 hi/lo (one launch) + rope tables + split X
    transpose_convert_all_kernel<<<dim3(64, 64, 4), dim3(32, 8)>>>(wq, wk, wv, wo);
    rope_table_kernel<<<(TOK * 64 + 255) / 256, 256>>>(pos);
    convert_split_x_kernel<<<(TOK * DD / 4 + 255) / 256, 256>>>(x);

    // 2. QKV projection with fused RMSNorm+RoPE+split epilogue
    gemm_qkv_kernel<<<dim3(QKVW / 128, TOK / 128), 256, GEMM_SMEM_BYTES>>>(qnw, knw);

    // 3. Flash attention (tensor cores)
    flash_kernel<<<dim3(LL / 128, NHEADS, BB), 256, FL_SMEM>>>();

    // 4. output projection
    gemm_out_kernel<<<dim3(DD / 128, TOK / 128), 256, GEMM_SMEM_BYTES>>>(out);
}